// round 1
// baseline (speedup 1.0000x reference)
#include <cuda_runtime.h>
#include <cstdint>

#define NBLK 128
#define TB   256
#define B_   512
#define S_   512
#define T_   511
#define H_   256
#define NTY  128
#define NG   1792
#define HP   260
#define GP   116
#define SMEM_BYTES 211456

__device__ float g_P[NTY * NG];
__device__ unsigned g_bar_cnt = 0;
__device__ unsigned g_bar_gen = 0;

__device__ __forceinline__ unsigned f2tf32(float x) {
    unsigned u;
    asm("cvt.rna.tf32.f32 %0, %1;" : "=r"(u) : "f"(x));
    return u;
}

__device__ __forceinline__ void mma8(float* d, unsigned a0, unsigned a1, unsigned a2, unsigned a3,
                                     unsigned b0, unsigned b1) {
    asm volatile(
        "mma.sync.aligned.m16n8k8.row.col.f32.tf32.tf32.f32 "
        "{%0,%1,%2,%3}, {%4,%5,%6,%7}, {%8,%9}, {%0,%1,%2,%3};"
        : "+f"(d[0]), "+f"(d[1]), "+f"(d[2]), "+f"(d[3])
        : "r"(a0), "r"(a1), "r"(a2), "r"(a3), "r"(b0), "r"(b1));
}

__device__ __forceinline__ float sigf(float x)   { return __fdividef(1.0f, 1.0f + __expf(-x)); }
__device__ __forceinline__ float tanhx(float x)  { return 1.0f - __fdividef(2.0f, __expf(2.0f * x) + 1.0f); }
__device__ __forceinline__ float softplusf(float x) { return x > 15.0f ? x : log1pf(__expf(x)); }

__device__ __forceinline__ void grid_barrier() {
    __syncthreads();
    if (threadIdx.x == 0) {
        volatile unsigned* genp = &g_bar_gen;
        unsigned gen = *genp;
        __threadfence();
        if (atomicAdd(&g_bar_cnt, 1u) == NBLK - 1u) {
            g_bar_cnt = 0u;
            __threadfence();
            *genp = gen + 1u;
        } else {
            while (*genp == gen) { __nanosleep(64); }
        }
        __threadfence();
    }
    __syncthreads();
}

__global__ void __launch_bounds__(TB, 1)
ctlstm_kernel(const int* __restrict__ types, const float* __restrict__ dtime,
              const float* __restrict__ emb, const float* __restrict__ Wc,
              const float* __restrict__ bc, const float* __restrict__ Wl,
              const float* __restrict__ bl, float* __restrict__ out)
{
    extern __shared__ char smem[];
    float2* Wf  = (float2*)smem;                    // 14*32*32 B-fragments (W_h slice, tf32)
    float*  h_s = (float*)(smem + 114688);          // 64 x HP (A tile)
    float*  gts = (float*)(smem + 181248);          // 64 x GP (gates)
    int*    tys = (int*)(smem + 210944);            // 64
    float*  dts = (float*)(smem + 211200);          // 64

    const int tid  = threadIdx.x;
    const int bb   = blockIdx.x >> 4;   // batch tile 0..7
    const int hb   = blockIdx.x & 15;   // hidden tile 0..15
    const int warp = tid >> 5;
    const int lane = tid & 31;
    const int gid  = lane >> 2;
    const int tig  = lane & 3;
    const int mw   = warp & 3;          // M sub-tile
    const int nw   = warp >> 2;         // N half

    float* intens = out;
    float* h_out  = out + (size_t)B_ * T_ * NTY;
    const size_t CH = (size_t)T_ * B_ * H_;
    float* c_out  = h_out + CH;
    float* cb_out = h_out + 2 * CH;
    float* de_out = h_out + 3 * CH;
    float* o_out  = h_out + 4 * CH;

    // ---- Phase 0a: pack this block's W_h slice into tf32 MMA B-fragments ----
    for (int e = tid; e < 14 * 32 * 32; e += TB) {
        int nf = e >> 10, kf = (e >> 5) & 31, ln = e & 31;
        int g8 = ln >> 2, t4 = ln & 3;
        int c  = nf * 8 + g8;                           // local col 0..111
        int n  = (c >> 4) * H_ + hb * 16 + (c & 15);    // global gate col
        int k  = kf * 8 + t4;
        float x = Wc[(size_t)(H_ + k) * NG + n];
        float y = Wc[(size_t)(H_ + k + 4) * NG + n];
        Wf[e] = make_float2(__uint_as_float(f2tf32(x)), __uint_as_float(f2tf32(y)));
    }
    // ---- Phase 0b: P[type] = emb_table[type] @ W_x + b_cell (1 type per block) ----
    {
        int ty = blockIdx.x;   // 0..127 == all possible type values
        if (tid < H_) h_s[tid] = emb[ty * H_ + tid];
        __syncthreads();
        for (int n = tid; n < NG; n += TB) {
            float acc = bc[n];
            #pragma unroll 8
            for (int k = 0; k < H_; k++) acc = fmaf(h_s[k], Wc[(size_t)k * NG + n], acc);
            g_P[ty * NG + n] = acc;
        }
    }
    grid_barrier();

    // ---- Phase 1: sequential CT-LSTM scan ----
    float cr[4], cbr[4];
    #pragma unroll
    for (int p = 0; p < 4; p++) { cr[p] = 0.f; cbr[p] = 0.f; }

    const int jj  = tid & 15;
    const int bl0 = tid >> 4;
    const int hid = hb * 16 + jj;

    for (int t = 0; t < T_; t++) {
        // stage h_{t-1} (B-tile x 256) into SMEM, converted RNA->tf32
        if (t > 0) {
            int row = tid >> 2, part = tid & 3;
            const float4* src = (const float4*)(h_out + (size_t)(t - 1) * (B_ * H_)
                                                + (size_t)(bb * 64 + row) * H_) + part * 16;
            float4* dst = (float4*)(h_s + row * HP + part * 64);
            #pragma unroll
            for (int i = 0; i < 16; i++) {
                float4 v = __ldcg(src + i);
                v.x = __uint_as_float(f2tf32(v.x));
                v.y = __uint_as_float(f2tf32(v.y));
                v.z = __uint_as_float(f2tf32(v.z));
                v.w = __uint_as_float(f2tf32(v.w));
                dst[i] = v;
            }
        }
        if (tid < 64) {
            int b = bb * 64 + tid;
            tys[tid] = __ldg(types + (size_t)b * S_ + t);
            dts[tid] = __ldg(dtime + (size_t)b * S_ + t + 1);
        }
        __syncthreads();

        if (t > 0) {
            float d[7][4];
            #pragma unroll
            for (int q = 0; q < 7; q++) {
                #pragma unroll
                for (int r = 0; r < 4; r++) d[q][r] = 0.f;
            }
            const float*  hrow = h_s + (mw * 16 + gid) * HP + tig;
            const float2* wb   = Wf + (size_t)(nw * 7) * 1024 + lane;
            #pragma unroll 2
            for (int kf = 0; kf < 32; kf++) {
                unsigned a0 = __float_as_uint(hrow[kf * 8]);
                unsigned a1 = __float_as_uint(hrow[kf * 8 + 8 * HP]);
                unsigned a2 = __float_as_uint(hrow[kf * 8 + 4]);
                unsigned a3 = __float_as_uint(hrow[kf * 8 + 8 * HP + 4]);
                #pragma unroll
                for (int q = 0; q < 7; q++) {
                    float2 bv = wb[(q * 32 + kf) * 32];
                    mma8(d[q], a0, a1, a2, a3, __float_as_uint(bv.x), __float_as_uint(bv.y));
                }
            }
            int r0 = mw * 16 + gid;
            #pragma unroll
            for (int q = 0; q < 7; q++) {
                int col = nw * 56 + q * 8 + 2 * tig;
                *(float2*)(gts + r0 * GP + col)       = make_float2(d[q][0], d[q][1]);
                *(float2*)(gts + (r0 + 8) * GP + col) = make_float2(d[q][2], d[q][3]);
            }
        }
        __syncthreads();

        // elementwise CT-LSTM update; c / c_bar live in registers across all steps
        {
            const size_t tb = (size_t)t * (B_ * H_);
            #pragma unroll
            for (int p = 0; p < 4; p++) {
                int blo = bl0 + p * 16;
                int b   = bb * 64 + blo;
                const float* Pr = g_P + (size_t)tys[blo] * NG + hid;
                float dt = dts[blo];
                float g0, g1, g2, g3, g4, g5, g6;
                if (t > 0) {
                    const float* gr = gts + blo * GP + jj;
                    g0 = gr[0];  g1 = gr[16]; g2 = gr[32]; g3 = gr[48];
                    g4 = gr[64]; g5 = gr[80]; g6 = gr[96];
                } else {
                    g0 = g1 = g2 = g3 = g4 = g5 = g6 = 0.f;
                }
                g0 += __ldg(Pr + 0 * H_); g1 += __ldg(Pr + 1 * H_);
                g2 += __ldg(Pr + 2 * H_); g3 += __ldg(Pr + 3 * H_);
                g4 += __ldg(Pr + 4 * H_); g5 += __ldg(Pr + 5 * H_);
                g6 += __ldg(Pr + 6 * H_);
                float iv = sigf(g0), fv = sigf(g1), zv = tanhx(g2), ov = sigf(g3);
                float ib = sigf(g4), fb = sigf(g5), de = softplusf(g6);
                float ci  = fv * cr[p] + iv * zv;
                float cbn = fb * cbr[p] + ib * zv;
                float ct  = cbn + (ci - cbn) * __expf(-de * dt);
                float hn  = ov * tanhx(ct);
                cr[p] = ct; cbr[p] = cbn;
                size_t idx = tb + (size_t)b * H_ + hid;
                h_out[idx] = hn;  c_out[idx] = ci;  cb_out[idx] = cbn;
                de_out[idx] = de; o_out[idx] = ov;
            }
        }
        grid_barrier();
    }

    // ---- Phase 2: intensity = softplus(h_out @ W_lam + b_lam), MMA tf32 ----
    float2* WfL = (float2*)smem;            // 16*32*32 fragments (128 KB)
    float*  h2  = (float*)(smem + 131072);  // 64 x HP
    for (int e = tid; e < 16 * 32 * 32; e += TB) {
        int nf = e >> 10, kf = (e >> 5) & 31, ln = e & 31;
        int g8 = ln >> 2, t4 = ln & 3;
        int n = nf * 8 + g8;
        int k = kf * 8 + t4;
        float x = Wl[(size_t)k * NTY + n];
        float y = Wl[(size_t)(k + 4) * NTY + n];
        WfL[e] = make_float2(__uint_as_float(f2tf32(x)), __uint_as_float(f2tf32(y)));
    }
    __syncthreads();

    const int NTILE = (T_ * B_) / 64;  // 4088 row tiles of 64
    for (int mt = blockIdx.x; mt < NTILE; mt += NBLK) {
        int r0 = mt * 64;
        int tt = r0 >> 9;       // timestep
        int b0 = r0 & 511;      // batch base
        {
            int row = tid >> 2, part = tid & 3;
            const float4* src = (const float4*)(h_out + (size_t)tt * (B_ * H_)
                                                + (size_t)(b0 + row) * H_) + part * 16;
            float4* dst = (float4*)(h2 + row * HP + part * 64);
            #pragma unroll
            for (int i = 0; i < 16; i++) {
                float4 v = __ldcg(src + i);
                v.x = __uint_as_float(f2tf32(v.x));
                v.y = __uint_as_float(f2tf32(v.y));
                v.z = __uint_as_float(f2tf32(v.z));
                v.w = __uint_as_float(f2tf32(v.w));
                dst[i] = v;
            }
        }
        __syncthreads();
        float d[8][4];
        #pragma unroll
        for (int q = 0; q < 8; q++) {
            #pragma unroll
            for (int r = 0; r < 4; r++) d[q][r] = 0.f;
        }
        const float*  hrow = h2 + (mw * 16 + gid) * HP + tig;
        const float2* wb   = WfL + (size_t)(nw * 8) * 1024 + lane;
        #pragma unroll 2
        for (int kf = 0; kf < 32; kf++) {
            unsigned a0 = __float_as_uint(hrow[kf * 8]);
            unsigned a1 = __float_as_uint(hrow[kf * 8 + 8 * HP]);
            unsigned a2 = __float_as_uint(hrow[kf * 8 + 4]);
            unsigned a3 = __float_as_uint(hrow[kf * 8 + 8 * HP + 4]);
            #pragma unroll
            for (int q = 0; q < 8; q++) {
                float2 bv = wb[(q * 32 + kf) * 32];
                mma8(d[q], a0, a1, a2, a3, __float_as_uint(bv.x), __float_as_uint(bv.y));
            }
        }
        int rl = mw * 16 + gid;
        #pragma unroll
        for (int q = 0; q < 8; q++) {
            int n0 = (nw * 8 + q) * 8 + 2 * tig;
            float bv0 = __ldg(bl + n0), bv1 = __ldg(bl + n0 + 1);
            size_t base = (size_t)(b0 + rl) * (T_ * NTY) + (size_t)tt * NTY + n0;
            float2 v0 = make_float2(softplusf(d[q][0] + bv0), softplusf(d[q][1] + bv1));
            *(float2*)(intens + base) = v0;
            size_t base2 = base + (size_t)8 * (T_ * NTY);
            float2 v1 = make_float2(softplusf(d[q][2] + bv0), softplusf(d[q][3] + bv1));
            *(float2*)(intens + base2) = v1;
        }
        __syncthreads();
    }
}

extern "C" void kernel_launch(void* const* d_in, const int* in_sizes, int n_in,
                              void* d_out, int out_size) {
    const int*   types = (const int*)d_in[0];
    const float* dtime = (const float*)d_in[1];
    const float* emb   = (const float*)d_in[2];
    const float* Wc    = (const float*)d_in[3];
    const float* bc    = (const float*)d_in[4];
    const float* Wl    = (const float*)d_in[5];
    const float* bl    = (const float*)d_in[6];
    cudaFuncSetAttribute(ctlstm_kernel, cudaFuncAttributeMaxDynamicSharedMemorySize, SMEM_BYTES);
    ctlstm_kernel<<<NBLK, TB, SMEM_BYTES>>>(types, dtime, emb, Wc, bc, Wl, bl, (float*)d_out);
}

// round 4
// speedup vs baseline: 1.5057x; 1.5057x over previous
#include <cuda_runtime.h>
#include <cstdint>

#define NBLK 128
#define TB   512
#define B_   512
#define S_   512
#define T_   511
#define H_   256
#define NTY  128
#define NG   1792
#define HP   260
#define GP   116

// scan-phase smem (floats/bytes from dynamic smem base)
#define OFF_WF  0            // 14 frags x 16 kf2 x 32 lanes x float4 = 114688 B (131072 reserved)
#define OFF_HS  131072       // 64 x 260 x 4 = 66560 B
#define OFF_GTS 197632       // 64 x 116 x 4 = 29696 B
#define SMEM_BYTES 227328
// phase-2 smem
#define OFF_WFL 0            // 16*32*32 float2 = 131072 B
#define OFF_H2  131072

__device__ float g_P[NTY * NG];
__device__ unsigned g_cnt_full = 0;
__device__ unsigned g_gen_full = 0;
__device__ unsigned g_cnt_grp[256];
__device__ unsigned g_gen_grp[256];

__device__ __forceinline__ unsigned f2tf32(float x) {
    unsigned u;
    asm("cvt.rna.tf32.f32 %0, %1;" : "=r"(u) : "f"(x));
    return u;
}
__device__ __forceinline__ float tf(float x) { return __uint_as_float(f2tf32(x)); }

__device__ __forceinline__ void mma8(float* d, unsigned a0, unsigned a1, unsigned a2, unsigned a3,
                                     unsigned b0, unsigned b1) {
    asm volatile(
        "mma.sync.aligned.m16n8k8.row.col.f32.tf32.tf32.f32 "
        "{%0,%1,%2,%3}, {%4,%5,%6,%7}, {%8,%9}, {%0,%1,%2,%3};"
        : "+f"(d[0]), "+f"(d[1]), "+f"(d[2]), "+f"(d[3])
        : "r"(a0), "r"(a1), "r"(a2), "r"(a3), "r"(b0), "r"(b1));
}

__device__ __forceinline__ float sigf(float x)   { return __fdividef(1.0f, 1.0f + __expf(-x)); }
__device__ __forceinline__ float tanhx(float x)  { return 1.0f - __fdividef(2.0f, __expf(2.0f * x) + 1.0f); }
__device__ __forceinline__ float softplusf(float x) { return x > 15.0f ? x : log1pf(__expf(x)); }

__device__ __forceinline__ void full_barrier() {
    __syncthreads();
    if (threadIdx.x == 0) {
        volatile unsigned* genp = &g_gen_full;
        unsigned gen = *genp;
        __threadfence();
        if (atomicAdd(&g_cnt_full, 1u) == NBLK - 1u) {
            g_cnt_full = 0u;
            __threadfence();
            *genp = gen + 1u;
        } else {
            while (*genp == gen) {}
        }
        __threadfence();
    }
    __syncthreads();
}

__global__ void __launch_bounds__(TB, 1)
ctlstm_kernel(const int* __restrict__ types, const float* __restrict__ dtime,
              const float* __restrict__ emb, const float* __restrict__ Wc,
              const float* __restrict__ bc, const float* __restrict__ Wl,
              const float* __restrict__ bl, float* __restrict__ out)
{
    extern __shared__ __align__(1024) char smem[];
    const int tid  = threadIdx.x;
    const int wid  = tid >> 5;
    const int lane = tid & 31;
    const int gid  = lane >> 2;
    const int tig  = lane & 3;
    const int bb   = blockIdx.x >> 4;   // batch tile 0..7 (64 rows)
    const int hb   = blockIdx.x & 15;   // hidden tile 0..15 (16 hids)

    float* intens = out;
    float* h_out  = out + (size_t)B_ * T_ * NTY;
    const size_t CH = (size_t)T_ * B_ * H_;
    float* c_out  = h_out + CH;
    float* cb_out = h_out + 2 * CH;
    float* de_out = h_out + 3 * CH;
    float* o_out  = h_out + 4 * CH;

    // ---- Phase 0a: pack W_h slice into tf32 MMA B-fragments, kf2-paired ----
    // entry e: f = e>>9 (frag 0..13), kf2 = (e>>5)&15, lane' = e&31 (g8 = ln>>2, t4 = ln&3)
    // frag f covers gate q = f>>1, hid cols (f&1)*8 + g8 within this block's 16-hid tile.
    for (int e = tid; e < 14 * 512; e += TB) {
        int f   = e >> 9;
        int kf2 = (e >> 5) & 15;
        int ln  = e & 31;
        int g8  = ln >> 2, t4 = ln & 3;
        int q = f >> 1, half = f & 1;
        int n = q * H_ + hb * 16 + half * 8 + g8;
        int k0 = kf2 * 16 + t4;
        float b0a = Wc[(size_t)(H_ + k0)      * NG + n];
        float b1a = Wc[(size_t)(H_ + k0 + 4)  * NG + n];
        float b0b = Wc[(size_t)(H_ + k0 + 8)  * NG + n];
        float b1b = Wc[(size_t)(H_ + k0 + 12) * NG + n];
        ((float4*)(smem + OFF_WF))[e] = make_float4(tf(b0a), tf(b1a), tf(b0b), tf(b1b));
    }
    // ---- Phase 0b: P[type] = emb_table[type] @ W_x + b_cell (1 type / block) ----
    {
        float* scr = (float*)(smem + OFF_HS);
        int ty = blockIdx.x;
        if (tid < H_) scr[tid] = emb[ty * H_ + tid];
        __syncthreads();
        for (int n = tid; n < NG; n += TB) {
            float acc = bc[n];
            #pragma unroll 8
            for (int k = 0; k < H_; k++) acc = fmaf(scr[k], Wc[(size_t)k * NG + n], acc);
            g_P[ty * NG + n] = acc;
        }
        __syncthreads();
    }
    full_barrier();

    // ---- Phase 1: sequential CT-LSTM scan ----
    const int mw = wid & 1;             // M half (32 rows)
    const int nw = wid >> 1;            // N quarter (4 frags)
    const int jj = tid & 15;            // hid within tile
    const int rb = tid >> 4;            // row 0..31; this thread handles rows rb, rb+32
    const int bA = bb * 64 + rb;
    const int bB = bA + 32;
    const int hid = hb * 16 + jj;

    float cst[2]  = {0.f, 0.f};
    float cbst[2] = {0.f, 0.f};

    volatile unsigned* genp = &g_gen_grp[bb * 32];
    unsigned* cntp = &g_cnt_grp[bb * 32];

    for (int t = 0; t < T_; t++) {
        // ---- prefetch gate-independent operands (hidden under stage+MMA) ----
        int   tyA = __ldg(types + (size_t)bA * S_ + t);
        int   tyB = __ldg(types + (size_t)bB * S_ + t);
        float dtA = __ldg(dtime + (size_t)bA * S_ + t + 1);
        float dtB = __ldg(dtime + (size_t)bB * S_ + t + 1);
        float pgv[2][7];
        {
            const float* PA = g_P + (size_t)tyA * NG + hid;
            const float* PB = g_P + (size_t)tyB * NG + hid;
            #pragma unroll
            for (int q = 0; q < 7; q++) {
                pgv[0][q] = __ldg(PA + q * H_);
                pgv[1][q] = __ldg(PB + q * H_);
            }
        }

        if (t > 0) {
            // ---- stage h_{t-1}: coalesced LDG, conflict-free STS.128 ----
            {
                int row = tid >> 3, inner = tid & 7;
                const float4* src = (const float4*)(h_out + (size_t)(t - 1) * (B_ * H_)
                                                    + (size_t)(bb * 64 + row) * H_);
                float* dst = (float*)(smem + OFF_HS) + row * HP;
                #pragma unroll
                for (int j = 0; j < 8; j++) {
                    int c4 = inner + 8 * j;
                    float4 v = __ldcg(src + c4);
                    v.x = tf(v.x); v.y = tf(v.y); v.z = tf(v.z); v.w = tf(v.w);
                    *(float4*)(dst + c4 * 4) = v;
                }
            }
            __syncthreads();

            // ---- gates = h @ W_h : warps 0..7, each m32 x n32 ----
            if (wid < 8) {
                float acc[2][4][4];
                #pragma unroll
                for (int s = 0; s < 2; s++)
                    #pragma unroll
                    for (int f = 0; f < 4; f++)
                        #pragma unroll
                        for (int r2 = 0; r2 < 4; r2++) acc[s][f][r2] = 0.f;
                const float*  hA = (const float*)(smem + OFF_HS) + (mw * 32 + gid) * HP + tig;
                const float4* wB = (const float4*)(smem + OFF_WF) + (size_t)(nw * 64) * 32 + lane;
                #pragma unroll 4
                for (int kf2 = 0; kf2 < 16; kf2++) {
                    float4 bv[4];
                    #pragma unroll
                    for (int f = 0; f < 4; f++) bv[f] = wB[(f * 16 + kf2) * 32];
                    #pragma unroll
                    for (int kk = 0; kk < 2; kk++) {
                        const float* hk = hA + kf2 * 16 + kk * 8;
                        unsigned a0 = __float_as_uint(hk[0]);
                        unsigned a1 = __float_as_uint(hk[8 * HP]);
                        unsigned a2 = __float_as_uint(hk[4]);
                        unsigned a3 = __float_as_uint(hk[8 * HP + 4]);
                        unsigned c0 = __float_as_uint(hk[16 * HP]);
                        unsigned c1 = __float_as_uint(hk[24 * HP]);
                        unsigned c2 = __float_as_uint(hk[16 * HP + 4]);
                        unsigned c3 = __float_as_uint(hk[24 * HP + 4]);
                        #pragma unroll
                        for (int f = 0; f < 4; f++) {
                            unsigned b0 = __float_as_uint(kk ? bv[f].z : bv[f].x);
                            unsigned b1 = __float_as_uint(kk ? bv[f].w : bv[f].y);
                            mma8(acc[0][f], a0, a1, a2, a3, b0, b1);
                            mma8(acc[1][f], c0, c1, c2, c3, b0, b1);
                        }
                    }
                }
                float* g = (float*)(smem + OFF_GTS);
                #pragma unroll
                for (int s = 0; s < 2; s++) {
                    #pragma unroll
                    for (int f = 0; f < 4; f++) {
                        int fg = nw * 4 + f;
                        if (fg < 14) {
                            int c  = fg * 8 + 2 * tig;
                            int r0 = mw * 32 + s * 16 + gid;
                            *(float2*)(g + r0 * GP + c)       = make_float2(acc[s][f][0], acc[s][f][1]);
                            *(float2*)(g + (r0 + 8) * GP + c) = make_float2(acc[s][f][2], acc[s][f][3]);
                        }
                    }
                }
            }
            __syncthreads();
        }

        // ---- elementwise CT-LSTM update (2 rows/thread, all 512 threads) ----
        float civ[2], cbv[2], dev[2], ovv[2];
        size_t idxA = 0, idxB = 0;
        {
            const float* gbase = (const float*)(smem + OFF_GTS);
            #pragma unroll
            for (int p = 0; p < 2; p++) {
                float g[7];
                #pragma unroll
                for (int q = 0; q < 7; q++) g[q] = pgv[p][q];
                if (t > 0) {
                    const float* gr = gbase + (rb + p * 32) * GP + jj;
                    #pragma unroll
                    for (int q = 0; q < 7; q++) g[q] += gr[q * 16];
                }
                float dt = p ? dtB : dtA;
                float iv = sigf(g[0]), fv = sigf(g[1]), zv = tanhx(g[2]), ov = sigf(g[3]);
                float ib = sigf(g[4]), fb = sigf(g[5]), de = softplusf(g[6]);
                float ci  = fv * cst[p] + iv * zv;
                float cb2 = fb * cbst[p] + ib * zv;
                float ct  = cb2 + (ci - cb2) * __expf(-de * dt);
                float hn  = ov * tanhx(ct);
                cst[p] = ct; cbst[p] = cb2;
                civ[p] = ci; cbv[p] = cb2; dev[p] = de; ovv[p] = ov;
                size_t idx = (size_t)t * (B_ * H_) + (size_t)(p ? bB : bA) * H_ + hid;
                if (p) idxB = idx; else idxA = idx;
                h_out[idx] = hn;   // critical-path store first
            }
        }
        __syncthreads();

        // ---- group barrier: arrive early, overlap remaining stores, wait late ----
        unsigned mygen = 0;
        if (tid == 0) {
            __threadfence();
            mygen = *genp;
            if (atomicAdd(cntp, 1u) == 15u) {
                *cntp = 0u;
                __threadfence();
                *genp = mygen + 1u;
            }
        }
        c_out[idxA]  = civ[0];  c_out[idxB]  = civ[1];
        cb_out[idxA] = cbv[0];  cb_out[idxB] = cbv[1];
        de_out[idxA] = dev[0];  de_out[idxB] = dev[1];
        o_out[idxA]  = ovv[0];  o_out[idxB]  = ovv[1];
        if (tid == 0) {
            while (*genp == mygen) {}
            __threadfence();
        }
        __syncthreads();
    }

    full_barrier();

    // ---- Phase 2: intensity = softplus(h_out @ W_lam + b_lam), tf32 HMMA ----
    {
        float2* WfL = (float2*)(smem + OFF_WFL);
        float*  h2  = (float*)(smem + OFF_H2);
        const int mw2 = wid & 3, nw2 = wid >> 2;
        for (int e = tid; e < 16 * 32 * 32; e += TB) {
            int nf = e >> 10, kf = (e >> 5) & 31, ln = e & 31;
            int g8 = ln >> 2, t4 = ln & 3;
            int n = nf * 8 + g8;
            int k = kf * 8 + t4;
            float x = Wl[(size_t)k * NTY + n];
            float y = Wl[(size_t)(k + 4) * NTY + n];
            WfL[e] = make_float2(tf(x), tf(y));
        }
        __syncthreads();

        const int NTILE = (T_ * B_) / 64;   // 4088
        for (int mt = blockIdx.x; mt < NTILE; mt += NBLK) {
            int r0t = mt * 64;
            int tt = r0t >> 9;
            int b0 = r0t & 511;
            {
                int row = tid >> 3, inner = tid & 7;
                const float4* src = (const float4*)(h_out + (size_t)tt * (B_ * H_)
                                                    + (size_t)(b0 + row) * H_);
                float* dst = h2 + row * HP;
                #pragma unroll
                for (int j = 0; j < 8; j++) {
                    int c4 = inner + 8 * j;
                    float4 v = __ldcg(src + c4);
                    v.x = tf(v.x); v.y = tf(v.y); v.z = tf(v.z); v.w = tf(v.w);
                    *(float4*)(dst + c4 * 4) = v;
                }
            }
            __syncthreads();
            float d[4][4];
            #pragma unroll
            for (int q = 0; q < 4; q++)
                #pragma unroll
                for (int r2 = 0; r2 < 4; r2++) d[q][r2] = 0.f;
            const float*  hrow = h2 + (mw2 * 16 + gid) * HP + tig;
            const float2* wb   = WfL + (size_t)(nw2 * 4) * 1024 + lane;
            #pragma unroll 2
            for (int kf = 0; kf < 32; kf++) {
                unsigned a0 = __float_as_uint(hrow[kf * 8]);
                unsigned a1 = __float_as_uint(hrow[kf * 8 + 8 * HP]);
                unsigned a2 = __float_as_uint(hrow[kf * 8 + 4]);
                unsigned a3 = __float_as_uint(hrow[kf * 8 + 8 * HP + 4]);
                #pragma unroll
                for (int q = 0; q < 4; q++) {
                    float2 bv = wb[(q * 32 + kf) * 32];
                    mma8(d[q], a0, a1, a2, a3, __float_as_uint(bv.x), __float_as_uint(bv.y));
                }
            }
            int rl = mw2 * 16 + gid;
            #pragma unroll
            for (int q = 0; q < 4; q++) {
                int n0 = (nw2 * 4 + q) * 8 + 2 * tig;
                float bv0 = __ldg(bl + n0), bv1 = __ldg(bl + n0 + 1);
                size_t base = (size_t)(b0 + rl) * (T_ * NTY) + (size_t)tt * NTY + n0;
                *(float2*)(intens + base) =
                    make_float2(softplusf(d[q][0] + bv0), softplusf(d[q][1] + bv1));
                size_t base2 = base + (size_t)8 * (T_ * NTY);
                *(float2*)(intens + base2) =
                    make_float2(softplusf(d[q][2] + bv0), softplusf(d[q][3] + bv1));
            }
            __syncthreads();
        }
    }
}

extern "C" void kernel_launch(void* const* d_in, const int* in_sizes, int n_in,
                              void* d_out, int out_size) {
    const int*   types = (const int*)d_in[0];
    const float* dtime = (const float*)d_in[1];
    const float* emb   = (const float*)d_in[2];
    const float* Wc    = (const float*)d_in[3];
    const float* bc    = (const float*)d_in[4];
    const float* Wl    = (const float*)d_in[5];
    const float* bl    = (const float*)d_in[6];
    cudaFuncSetAttribute(ctlstm_kernel, cudaFuncAttributeMaxDynamicSharedMemorySize, SMEM_BYTES);
    ctlstm_kernel<<<NBLK, TB, SMEM_BYTES>>>(types, dtime, emb, Wc, bc, Wl, bl, (float*)d_out);
}

// round 5
// speedup vs baseline: 1.8356x; 1.2191x over previous
#include <cuda_runtime.h>
#include <cstdint>

#define NBLK 128
#define TB   512
#define B_   512
#define S_   512
#define T_   511
#define H_   256
#define NTY  128
#define NG   1792
#define HP   260
#define GP   116

// ---- scan-phase smem ----
// WF: 14 nf x 8 kf2 x 32 lanes x uint4 = 57344 B  (bf16 B fragments, kf-paired)
// AF: 4 mt x 16 kf x 32 lanes x uint4 = 32768 B   (bf16 A fragments)
// GTS: 64 x 116 x 4 = 29696 B
#define OFF_WF  0
#define OFF_AF  57344
#define OFF_GTS 90112
// ---- phase-2 smem ----
#define OFF_WFL 0            // 16*32*32 float2 = 131072 B
#define OFF_H2  131072       // 64 x 260 x 4 = 66560 B
#define SMEM_BYTES 197632

__device__ float g_P[NTY * NG];
__device__ unsigned g_cnt_full = 0;
__device__ unsigned g_gen_full = 0;
__device__ unsigned g_cnt_grp[256];
__device__ unsigned g_gen_grp[256];

__device__ __forceinline__ unsigned f2tf32(float x) {
    unsigned u;
    asm("cvt.rna.tf32.f32 %0, %1;" : "=r"(u) : "f"(x));
    return u;
}
__device__ __forceinline__ float tf(float x) { return __uint_as_float(f2tf32(x)); }

// pack two f32 into bf16x2: lo -> lower half, hi -> upper half
__device__ __forceinline__ unsigned packbf(float lo, float hi) {
    unsigned r;
    asm("cvt.rn.bf16x2.f32 %0, %1, %2;" : "=r"(r) : "f"(hi), "f"(lo));
    return r;
}

__device__ __forceinline__ void mma16(float* d, uint4 a, unsigned b0, unsigned b1) {
    asm volatile(
        "mma.sync.aligned.m16n8k16.row.col.f32.bf16.bf16.f32 "
        "{%0,%1,%2,%3}, {%4,%5,%6,%7}, {%8,%9}, {%0,%1,%2,%3};"
        : "+f"(d[0]), "+f"(d[1]), "+f"(d[2]), "+f"(d[3])
        : "r"(a.x), "r"(a.y), "r"(a.z), "r"(a.w), "r"(b0), "r"(b1));
}
__device__ __forceinline__ void mma8(float* d, unsigned a0, unsigned a1, unsigned a2, unsigned a3,
                                     unsigned b0, unsigned b1) {
    asm volatile(
        "mma.sync.aligned.m16n8k8.row.col.f32.tf32.tf32.f32 "
        "{%0,%1,%2,%3}, {%4,%5,%6,%7}, {%8,%9}, {%0,%1,%2,%3};"
        : "+f"(d[0]), "+f"(d[1]), "+f"(d[2]), "+f"(d[3])
        : "r"(a0), "r"(a1), "r"(a2), "r"(a3), "r"(b0), "r"(b1));
}

__device__ __forceinline__ float sigf(float x)   { return __fdividef(1.0f, 1.0f + __expf(-x)); }
__device__ __forceinline__ float tanhx(float x)  { return 1.0f - __fdividef(2.0f, __expf(2.0f * x) + 1.0f); }
__device__ __forceinline__ float softplusf(float x) { return x > 15.0f ? x : log1pf(__expf(x)); }

__device__ __forceinline__ void full_barrier() {
    __syncthreads();
    if (threadIdx.x == 0) {
        volatile unsigned* genp = &g_gen_full;
        unsigned gen = *genp;
        __threadfence();
        if (atomicAdd(&g_cnt_full, 1u) == NBLK - 1u) {
            g_cnt_full = 0u;
            __threadfence();
            *genp = gen + 1u;
        } else {
            while (*genp == gen) {}
        }
        __threadfence();
    }
    __syncthreads();
}

__global__ void __launch_bounds__(TB, 1)
ctlstm_kernel(const int* __restrict__ types, const float* __restrict__ dtime,
              const float* __restrict__ emb, const float* __restrict__ Wc,
              const float* __restrict__ bc, const float* __restrict__ Wl,
              const float* __restrict__ bl, float* __restrict__ out)
{
    extern __shared__ __align__(1024) char smem[];
    const int tid  = threadIdx.x;
    const int wid  = tid >> 5;
    const int lane = tid & 31;
    const int gid  = lane >> 2;
    const int tig  = lane & 3;
    const int bb   = blockIdx.x >> 4;   // batch tile 0..7 (64 rows)
    const int hb   = blockIdx.x & 15;   // hidden tile 0..15 (16 hids)

    float* intens = out;
    float* h_out  = out + (size_t)B_ * T_ * NTY;
    const size_t CH = (size_t)T_ * B_ * H_;
    float* c_out  = h_out + CH;
    float* cb_out = h_out + 2 * CH;
    float* de_out = h_out + 3 * CH;
    float* o_out  = h_out + 4 * CH;

    // ---- Phase 0a: pack W_h slice -> bf16 B fragments (m16n8k16), kf-paired ----
    // WF[nf][kf2][lane] = uint4(b0@kf=2kf2, b1@kf=2kf2, b0@kf=2kf2+1, b1@kf=2kf2+1)
    for (int e = tid; e < 14 * 8 * 32; e += TB) {
        int nf  = e >> 8;
        int kf2 = (e >> 5) & 7;
        int ln  = e & 31;
        int g8  = ln >> 2, t4 = ln & 3;
        int q = nf >> 1;
        int n = q * H_ + hb * 16 + (nf & 1) * 8 + g8;
        int kb0 = kf2 * 32;          // kf = 2*kf2
        int kb1 = kf2 * 32 + 16;     // kf = 2*kf2+1
        const float* Wh = Wc + (size_t)H_ * NG + n;
        unsigned b0 = packbf(Wh[(size_t)(kb0 + 2 * t4)     * NG], Wh[(size_t)(kb0 + 2 * t4 + 1) * NG]);
        unsigned b1 = packbf(Wh[(size_t)(kb0 + 8 + 2 * t4) * NG], Wh[(size_t)(kb0 + 9 + 2 * t4) * NG]);
        unsigned b2 = packbf(Wh[(size_t)(kb1 + 2 * t4)     * NG], Wh[(size_t)(kb1 + 2 * t4 + 1) * NG]);
        unsigned b3 = packbf(Wh[(size_t)(kb1 + 8 + 2 * t4) * NG], Wh[(size_t)(kb1 + 9 + 2 * t4) * NG]);
        ((uint4*)(smem + OFF_WF))[e] = make_uint4(b0, b1, b2, b3);
    }
    // ---- Phase 0b: P[type] = emb_table[type] @ W_x + b_cell (1 type / block) ----
    {
        float* scr = (float*)(smem + OFF_AF);
        int ty = blockIdx.x;
        if (tid < H_) scr[tid] = emb[ty * H_ + tid];
        __syncthreads();
        for (int n = tid; n < NG; n += TB) {
            float acc = bc[n];
            #pragma unroll 8
            for (int k = 0; k < H_; k++) acc = fmaf(scr[k], Wc[(size_t)k * NG + n], acc);
            g_P[ty * NG + n] = acc;
        }
        __syncthreads();
    }
    full_barrier();

    // ---- Phase 1: sequential CT-LSTM scan ----
    const int mw = wid & 1;             // M half (32 rows = m16 tiles 2mw, 2mw+1)
    const int nw = wid >> 1;            // N quarter (4 n-frags)
    const int jj = tid & 15;            // hid within tile
    const int rb = tid >> 4;            // row 0..31; handles rows rb, rb+32
    const int bA = bb * 64 + rb;
    const int bB = bA + 32;
    const int hid = hb * 16 + jj;

    // staging decomposition for fragment-major A scatter
    const int s_r    = tid >> 3;        // row 0..63
    const int s_i    = tid & 7;
    const int s_mt   = s_r >> 4;
    const int s_gid  = s_r & 7;
    const int s_half = (s_r >> 3) & 1;
    uint32_t* AFw = (uint32_t*)(smem + OFF_AF);
    const int s_base = s_mt * 16 * 32 * 4;   // word offset of this row's mt group

    float cst[2]  = {0.f, 0.f};
    float cbst[2] = {0.f, 0.f};

    volatile unsigned* genp = &g_gen_grp[bb * 32];
    unsigned* cntp = &g_cnt_grp[bb * 32];

    for (int t = 0; t < T_; t++) {
        // ---- prefetch gate-independent operands ----
        int   tyA = __ldg(types + (size_t)bA * S_ + t);
        int   tyB = __ldg(types + (size_t)bB * S_ + t);
        float dtA = __ldg(dtime + (size_t)bA * S_ + t + 1);
        float dtB = __ldg(dtime + (size_t)bB * S_ + t + 1);
        float pgv[2][7];
        {
            const float* PA = g_P + (size_t)tyA * NG + hid;
            const float* PB = g_P + (size_t)tyB * NG + hid;
            #pragma unroll
            for (int q = 0; q < 7; q++) {
                pgv[0][q] = __ldg(PA + q * H_);
                pgv[1][q] = __ldg(PB + q * H_);
            }
        }

        if (t > 0) {
            // ---- stage h_{t-1} -> bf16 A fragments (fragment-major scatter) ----
            {
                const float4* src = (const float4*)(h_out + (size_t)(t - 1) * (B_ * H_)
                                                    + (size_t)(bb * 64 + s_r) * H_);
                #pragma unroll
                for (int j = 0; j < 8; j++) {
                    int c4 = s_i + 8 * j;
                    float4 v = __ldcg(src + c4);
                    unsigned w0 = packbf(v.x, v.y);   // word c = 2*c4
                    unsigned w1 = packbf(v.z, v.w);   // word c = 2*c4+1
                    #pragma unroll
                    for (int s = 0; s < 2; s++) {
                        int c  = 2 * c4 + s;
                        int kf = c >> 3, cc = c & 7;
                        int kh = cc >> 2, t4 = cc & 3;
                        int idx = s_base + (kf * 32 + s_gid * 4 + t4) * 4 + kh * 2 + s_half;
                        AFw[idx] = s ? w1 : w0;
                    }
                }
            }
            __syncthreads();

            // ---- gates = h @ W_h : warps 0..7, each m32 x n32, bf16 m16n8k16 ----
            if (wid < 8) {
                float acc[2][4][4];
                #pragma unroll
                for (int m = 0; m < 2; m++)
                    #pragma unroll
                    for (int f = 0; f < 4; f++)
                        #pragma unroll
                        for (int r2 = 0; r2 < 4; r2++) acc[m][f][r2] = 0.f;
                const uint4* AFp = (const uint4*)(smem + OFF_AF) + (mw * 2 * 16) * 32 + lane;
                const uint4* WFp = (const uint4*)(smem + OFF_WF) + (nw * 4 * 8) * 32 + lane;
                #pragma unroll
                for (int kf2 = 0; kf2 < 8; kf2++) {
                    uint4 bv[4];
                    #pragma unroll
                    for (int f = 0; f < 4; f++) bv[f] = WFp[(f * 8 + kf2) * 32];
                    uint4 a0e = AFp[(2 * kf2) * 32];
                    uint4 a0o = AFp[(2 * kf2 + 1) * 32];
                    uint4 a1e = AFp[(16 + 2 * kf2) * 32];
                    uint4 a1o = AFp[(16 + 2 * kf2 + 1) * 32];
                    #pragma unroll
                    for (int f = 0; f < 4; f++) {
                        mma16(acc[0][f], a0e, bv[f].x, bv[f].y);
                        mma16(acc[1][f], a1e, bv[f].x, bv[f].y);
                        mma16(acc[0][f], a0o, bv[f].z, bv[f].w);
                        mma16(acc[1][f], a1o, bv[f].z, bv[f].w);
                    }
                }
                float* g = (float*)(smem + OFF_GTS);
                #pragma unroll
                for (int m = 0; m < 2; m++) {
                    #pragma unroll
                    for (int f = 0; f < 4; f++) {
                        int fg = nw * 4 + f;
                        if (fg < 14) {
                            int c  = fg * 8 + 2 * tig;
                            int r0 = mw * 32 + m * 16 + gid;
                            *(float2*)(g + r0 * GP + c)       = make_float2(acc[m][f][0], acc[m][f][1]);
                            *(float2*)(g + (r0 + 8) * GP + c) = make_float2(acc[m][f][2], acc[m][f][3]);
                        }
                    }
                }
            }
            __syncthreads();
        }

        // ---- elementwise CT-LSTM update (2 rows/thread) ----
        float civ[2], cbv[2], dev[2], ovv[2];
        size_t idxA = 0, idxB = 0;
        {
            const float* gbase = (const float*)(smem + OFF_GTS);
            #pragma unroll
            for (int p = 0; p < 2; p++) {
                float g[7];
                #pragma unroll
                for (int q = 0; q < 7; q++) g[q] = pgv[p][q];
                if (t > 0) {
                    const float* gr = gbase + (rb + p * 32) * GP + jj;
                    #pragma unroll
                    for (int q = 0; q < 7; q++) g[q] += gr[q * 16];
                }
                float dt = p ? dtB : dtA;
                float iv = sigf(g[0]), fv = sigf(g[1]), zv = tanhx(g[2]), ov = sigf(g[3]);
                float ib = sigf(g[4]), fb = sigf(g[5]), de = softplusf(g[6]);
                float ci  = fv * cst[p] + iv * zv;
                float cb2 = fb * cbst[p] + ib * zv;
                float ct  = cb2 + (ci - cb2) * __expf(-de * dt);
                float hn  = ov * tanhx(ct);
                cst[p] = ct; cbst[p] = cb2;
                civ[p] = ci; cbv[p] = cb2; dev[p] = de; ovv[p] = ov;
                size_t idx = (size_t)t * (B_ * H_) + (size_t)(p ? bB : bA) * H_ + hid;
                if (p) idxB = idx; else idxA = idx;
                h_out[idx] = hn;   // critical-path store first
            }
        }
        __syncthreads();

        // ---- group barrier: arrive early, overlap remaining stores, wait late ----
        unsigned mygen = 0;
        if (tid == 0) {
            __threadfence();
            mygen = *genp;
            if (atomicAdd(cntp, 1u) == 15u) {
                *cntp = 0u;
                __threadfence();
                *genp = mygen + 1u;
            }
        }
        c_out[idxA]  = civ[0];  c_out[idxB]  = civ[1];
        cb_out[idxA] = cbv[0];  cb_out[idxB] = cbv[1];
        de_out[idxA] = dev[0];  de_out[idxB] = dev[1];
        o_out[idxA]  = ovv[0];  o_out[idxB]  = ovv[1];
        if (tid == 0) {
            while (*genp == mygen) {}
            __threadfence();
        }
        __syncthreads();
    }

    full_barrier();

    // ---- Phase 2: intensity = softplus(h_out @ W_lam + b_lam), tf32 HMMA ----
    {
        float2* WfL = (float2*)(smem + OFF_WFL);
        float*  h2  = (float*)(smem + OFF_H2);
        const int mw2 = wid & 3, nw2 = wid >> 2;
        for (int e = tid; e < 16 * 32 * 32; e += TB) {
            int nf = e >> 10, kf = (e >> 5) & 31, ln = e & 31;
            int g8 = ln >> 2, t4 = ln & 3;
            int n = nf * 8 + g8;
            int k = kf * 8 + t4;
            float x = Wl[(size_t)k * NTY + n];
            float y = Wl[(size_t)(k + 4) * NTY + n];
            WfL[e] = make_float2(tf(x), tf(y));
        }
        __syncthreads();

        const int NTILE = (T_ * B_) / 64;   // 4088
        for (int mt = blockIdx.x; mt < NTILE; mt += NBLK) {
            int r0t = mt * 64;
            int tt = r0t >> 9;
            int b0 = r0t & 511;
            {
                int row = tid >> 3, inner = tid & 7;
                const float4* src = (const float4*)(h_out + (size_t)tt * (B_ * H_)
                                                    + (size_t)(b0 + row) * H_);
                float* dst = h2 + row * HP;
                #pragma unroll
                for (int j = 0; j < 8; j++) {
                    int c4 = inner + 8 * j;
                    float4 v = __ldcg(src + c4);
                    v.x = tf(v.x); v.y = tf(v.y); v.z = tf(v.z); v.w = tf(v.w);
                    *(float4*)(dst + c4 * 4) = v;
                }
            }
            __syncthreads();
            float d[4][4];
            #pragma unroll
            for (int q = 0; q < 4; q++)
                #pragma unroll
                for (int r2 = 0; r2 < 4; r2++) d[q][r2] = 0.f;
            const float*  hrow = h2 + (mw2 * 16 + gid) * HP + tig;
            const float2* wb   = WfL + (size_t)(nw2 * 4) * 1024 + lane;
            #pragma unroll 2
            for (int kf = 0; kf < 32; kf++) {
                unsigned a0 = __float_as_uint(hrow[kf * 8]);
                unsigned a1 = __float_as_uint(hrow[kf * 8 + 8 * HP]);
                unsigned a2 = __float_as_uint(hrow[kf * 8 + 4]);
                unsigned a3 = __float_as_uint(hrow[kf * 8 + 8 * HP + 4]);
                #pragma unroll
                for (int q = 0; q < 4; q++) {
                    float2 bv = wb[(q * 32 + kf) * 32];
                    mma8(d[q], a0, a1, a2, a3, __float_as_uint(bv.x), __float_as_uint(bv.y));
                }
            }
            int rl = mw2 * 16 + gid;
            #pragma unroll
            for (int q = 0; q < 4; q++) {
                int n0 = (nw2 * 4 + q) * 8 + 2 * tig;
                float bv0 = __ldg(bl + n0), bv1 = __ldg(bl + n0 + 1);
                size_t base = (size_t)(b0 + rl) * (T_ * NTY) + (size_t)tt * NTY + n0;
                *(float2*)(intens + base) =
                    make_float2(softplusf(d[q][0] + bv0), softplusf(d[q][1] + bv1));
                size_t base2 = base + (size_t)8 * (T_ * NTY);
                *(float2*)(intens + base2) =
                    make_float2(softplusf(d[q][2] + bv0), softplusf(d[q][3] + bv1));
            }
            __syncthreads();
        }
    }
}

extern "C" void kernel_launch(void* const* d_in, const int* in_sizes, int n_in,
                              void* d_out, int out_size) {
    const int*   types = (const int*)d_in[0];
    const float* dtime = (const float*)d_in[1];
    const float* emb   = (const float*)d_in[2];
    const float* Wc    = (const float*)d_in[3];
    const float* bc    = (const float*)d_in[4];
    const float* Wl    = (const float*)d_in[5];
    const float* bl    = (const float*)d_in[6];
    cudaFuncSetAttribute(ctlstm_kernel, cudaFuncAttributeMaxDynamicSharedMemorySize, SMEM_BYTES);
    ctlstm_kernel<<<NBLK, TB, SMEM_BYTES>>>(types, dtime, emb, Wc, bc, Wl, bl, (float*)d_out);
}

// round 6
// speedup vs baseline: 1.9753x; 1.0761x over previous
#include <cuda_runtime.h>
#include <cstdint>

#define NBLK 128
#define TB   512
#define B_   512
#define S_   512
#define T_   511
#define H_   256
#define NTY  128
#define NG   1792
#define HP   260
#define GP   116

// ---- scan-phase smem ----
#define OFF_WF  0            // 14 nf x 8 kf2 x 32 lanes x uint4 = 57344 B
#define OFF_AF  57344        // 4 mt x 16 kf x 32 lanes x uint4 = 32768 B
#define OFF_GTS 90112        // 64 x 116 x 4 = 29696 B
// ---- phase-2 smem ----
#define OFF_WFL 0
#define OFF_H2  131072
#define SMEM_BYTES 197632

__device__ float g_P[NTY * NG];
__device__ unsigned g_cnt_full = 0;
__device__ unsigned g_gen_full = 0;
__device__ unsigned g_cnt_grp[256];
__device__ unsigned g_gen_grp[256];

__device__ __forceinline__ unsigned f2tf32(float x) {
    unsigned u;
    asm("cvt.rna.tf32.f32 %0, %1;" : "=r"(u) : "f"(x));
    return u;
}
__device__ __forceinline__ float tf(float x) { return __uint_as_float(f2tf32(x)); }

// pack two f32 into bf16x2: lo -> lower half, hi -> upper half
__device__ __forceinline__ unsigned packbf(float lo, float hi) {
    unsigned r;
    asm("cvt.rn.bf16x2.f32 %0, %1, %2;" : "=r"(r) : "f"(hi), "f"(lo));
    return r;
}

__device__ __forceinline__ void mma16(float* d, uint4 a, unsigned b0, unsigned b1) {
    asm volatile(
        "mma.sync.aligned.m16n8k16.row.col.f32.bf16.bf16.f32 "
        "{%0,%1,%2,%3}, {%4,%5,%6,%7}, {%8,%9}, {%0,%1,%2,%3};"
        : "+f"(d[0]), "+f"(d[1]), "+f"(d[2]), "+f"(d[3])
        : "r"(a.x), "r"(a.y), "r"(a.z), "r"(a.w), "r"(b0), "r"(b1));
}
__device__ __forceinline__ void mma8(float* d, unsigned a0, unsigned a1, unsigned a2, unsigned a3,
                                     unsigned b0, unsigned b1) {
    asm volatile(
        "mma.sync.aligned.m16n8k8.row.col.f32.tf32.tf32.f32 "
        "{%0,%1,%2,%3}, {%4,%5,%6,%7}, {%8,%9}, {%0,%1,%2,%3};"
        : "+f"(d[0]), "+f"(d[1]), "+f"(d[2]), "+f"(d[3])
        : "r"(a0), "r"(a1), "r"(a2), "r"(a3), "r"(b0), "r"(b1));
}

__device__ __forceinline__ float sigf(float x)   { return __fdividef(1.0f, 1.0f + __expf(-x)); }
__device__ __forceinline__ float tanhx(float x)  { return 1.0f - __fdividef(2.0f, __expf(2.0f * x) + 1.0f); }
__device__ __forceinline__ float softplusf(float x) {
    return x > 15.0f ? x : __logf(1.0f + __expf(x));
}

__device__ __forceinline__ void full_barrier() {
    __syncthreads();
    if (threadIdx.x == 0) {
        volatile unsigned* genp = &g_gen_full;
        unsigned gen = *genp;
        __threadfence();
        if (atomicAdd(&g_cnt_full, 1u) == NBLK - 1u) {
            g_cnt_full = 0u;
            __threadfence();
            *genp = gen + 1u;
        } else {
            while (*genp == gen) {}
        }
        __threadfence();
    }
    __syncthreads();
}

__global__ void __launch_bounds__(TB, 1)
ctlstm_kernel(const int* __restrict__ types, const float* __restrict__ dtime,
              const float* __restrict__ emb, const float* __restrict__ Wc,
              const float* __restrict__ bc, const float* __restrict__ Wl,
              const float* __restrict__ bl, float* __restrict__ out)
{
    extern __shared__ __align__(1024) char smem[];
    const int tid  = threadIdx.x;
    const int wid  = tid >> 5;
    const int lane = tid & 31;
    const int gid  = lane >> 2;
    const int tig  = lane & 3;
    const int bb   = blockIdx.x >> 4;   // batch tile 0..7 (64 rows)
    const int hb   = blockIdx.x & 15;   // hidden tile 0..15 (16 hids)

    float* intens = out;
    float* h_out  = out + (size_t)B_ * T_ * NTY;
    const size_t CH = (size_t)T_ * B_ * H_;
    float* c_out  = h_out + CH;
    float* cb_out = h_out + 2 * CH;
    float* de_out = h_out + 3 * CH;
    float* o_out  = h_out + 4 * CH;

    // ---- Phase 0a: pack W_h slice -> bf16 B fragments (m16n8k16), kf-paired ----
    // k-permutation: fragment slot (kf, t4, kh) holds global k-pair
    //   w = 2*(kh*4 + t4) + 16*(kf>>1) + (kf&1)   (k = 2w, 2w+1)
    for (int e = tid; e < 14 * 8 * 32; e += TB) {
        int nf  = e >> 8;
        int kf2 = (e >> 5) & 7;
        int ln  = e & 31;
        int g8  = ln >> 2, t4 = ln & 3;
        int q = nf >> 1;
        int n = q * H_ + hb * 16 + (nf & 1) * 8 + g8;
        const float* Wh = Wc + (size_t)H_ * NG + n;
        unsigned bw[4];
        #pragma unroll
        for (int kk = 0; kk < 2; kk++) {
            int kf = 2 * kf2 + kk;
            #pragma unroll
            for (int kh = 0; kh < 2; kh++) {
                int w  = 2 * (kh * 4 + t4) + 16 * (kf >> 1) + (kf & 1);
                int k0 = 2 * w;
                bw[kk * 2 + kh] = packbf(Wh[(size_t)k0 * NG], Wh[(size_t)(k0 + 1) * NG]);
            }
        }
        ((uint4*)(smem + OFF_WF))[e] = make_uint4(bw[0], bw[1], bw[2], bw[3]);
    }
    // ---- Phase 0b: P[type] = emb_table[type] @ W_x + b_cell (1 type / block) ----
    {
        float* scr = (float*)(smem + OFF_AF);
        int ty = blockIdx.x;
        if (tid < H_) scr[tid] = emb[ty * H_ + tid];
        __syncthreads();
        for (int n = tid; n < NG; n += TB) {
            float acc = bc[n];
            #pragma unroll 8
            for (int k = 0; k < H_; k++) acc = fmaf(scr[k], Wc[(size_t)k * NG + n], acc);
            g_P[ty * NG + n] = acc;
        }
        __syncthreads();
    }
    full_barrier();

    // ---- Phase 1: sequential CT-LSTM scan ----
    const int mw = wid & 1;             // M half
    const int nw = wid >> 1;            // N quarter
    const int jj = tid & 15;            // hid within tile
    const int rb = tid >> 4;            // row 0..31; handles rows rb, rb+32
    const int bA = bb * 64 + rb;
    const int bB = bA + 32;
    const int hid = hb * 16 + jj;

    // staging decomposition: warp w covers rows mt*16 + {2q,2q+1,2q+8,2q+9}
    const int s_mt   = wid >> 2;
    const int s_q    = wid & 3;
    const int s_rr   = lane >> 3;            // 0..3 row selector within warp
    const int s_i    = lane & 7;             // 8 lanes per row
    const int s_gid  = 2 * s_q + (s_rr & 1);
    const int s_half = s_rr >> 1;
    const int s_row  = s_mt * 16 + s_gid + s_half * 8;
    const int s_t4   = s_i & 3;
    const int s_kh   = (s_i >> 2) & 1;
    uint32_t* AFw = (uint32_t*)(smem + OFF_AF);
    const int s_base = s_mt * 2048 + (s_gid * 4 + s_t4) * 4 + s_kh * 2 + s_half;

    float cst[2]  = {0.f, 0.f};
    float cbst[2] = {0.f, 0.f};

    volatile unsigned* genp = &g_gen_grp[bb * 32];
    unsigned* cntp = &g_cnt_grp[bb * 32];

    for (int t = 0; t < T_; t++) {
        // ---- prefetch gate-independent operands ----
        int   tyA = __ldg(types + (size_t)bA * S_ + t);
        int   tyB = __ldg(types + (size_t)bB * S_ + t);
        float dtA = __ldg(dtime + (size_t)bA * S_ + t + 1);
        float dtB = __ldg(dtime + (size_t)bB * S_ + t + 1);
        float pgv[2][7];
        {
            const float* PA = g_P + (size_t)tyA * NG + hid;
            const float* PB = g_P + (size_t)tyB * NG + hid;
            #pragma unroll
            for (int q = 0; q < 7; q++) {
                pgv[0][q] = __ldg(PA + q * H_);
                pgv[1][q] = __ldg(PB + q * H_);
            }
        }

        if (t > 0) {
            // ---- stage h_{t-1} -> bf16 A fragments (conflict-free scatter) ----
            {
                const float4* src = (const float4*)(h_out + (size_t)(t - 1) * (B_ * H_)
                                                    + (size_t)(bb * 64 + s_row) * H_);
                #pragma unroll
                for (int j = 0; j < 8; j++) {
                    int c4 = s_i + 8 * j;
                    float4 v = __ldcg(src + c4);
                    unsigned w0 = packbf(v.x, v.y);   // k-pair w = 2c4   -> kf = 2j
                    unsigned w1 = packbf(v.z, v.w);   // k-pair w = 2c4+1 -> kf = 2j+1
                    AFw[s_base + (2 * j)     * 128] = w0;
                    AFw[s_base + (2 * j + 1) * 128] = w1;
                }
            }
            __syncthreads();

            // ---- gates = h @ W_h : warps 0..7, each m32 x n32, bf16 m16n8k16 ----
            if (wid < 8) {
                float acc[2][4][4];
                #pragma unroll
                for (int m = 0; m < 2; m++)
                    #pragma unroll
                    for (int f = 0; f < 4; f++)
                        #pragma unroll
                        for (int r2 = 0; r2 < 4; r2++) acc[m][f][r2] = 0.f;
                const uint4* AFp = (const uint4*)(smem + OFF_AF) + (mw * 2 * 16) * 32 + lane;
                const uint4* WFp = (const uint4*)(smem + OFF_WF) + (nw * 4 * 8) * 32 + lane;
                #pragma unroll
                for (int kf2 = 0; kf2 < 8; kf2++) {
                    uint4 bv[4];
                    #pragma unroll
                    for (int f = 0; f < 4; f++) bv[f] = WFp[(f * 8 + kf2) * 32];
                    uint4 a0e = AFp[(2 * kf2) * 32];
                    uint4 a0o = AFp[(2 * kf2 + 1) * 32];
                    uint4 a1e = AFp[(16 + 2 * kf2) * 32];
                    uint4 a1o = AFp[(16 + 2 * kf2 + 1) * 32];
                    #pragma unroll
                    for (int f = 0; f < 4; f++) {
                        mma16(acc[0][f], a0e, bv[f].x, bv[f].y);
                        mma16(acc[1][f], a1e, bv[f].x, bv[f].y);
                        mma16(acc[0][f], a0o, bv[f].z, bv[f].w);
                        mma16(acc[1][f], a1o, bv[f].z, bv[f].w);
                    }
                }
                float* g = (float*)(smem + OFF_GTS);
                #pragma unroll
                for (int m = 0; m < 2; m++) {
                    #pragma unroll
                    for (int f = 0; f < 4; f++) {
                        int fg = nw * 4 + f;
                        if (fg < 14) {
                            int c  = fg * 8 + 2 * tig;
                            int r0 = mw * 32 + m * 16 + gid;
                            *(float2*)(g + r0 * GP + c)       = make_float2(acc[m][f][0], acc[m][f][1]);
                            *(float2*)(g + (r0 + 8) * GP + c) = make_float2(acc[m][f][2], acc[m][f][3]);
                        }
                    }
                }
            }
            __syncthreads();
        }

        // ---- elementwise CT-LSTM update (2 rows/thread) ----
        float civ[2], cbv[2], dev[2], ovv[2];
        size_t idxA = 0, idxB = 0;
        {
            const float* gbase = (const float*)(smem + OFF_GTS);
            #pragma unroll
            for (int p = 0; p < 2; p++) {
                float g[7];
                #pragma unroll
                for (int q = 0; q < 7; q++) g[q] = pgv[p][q];
                if (t > 0) {
                    const float* gr = gbase + (rb + p * 32) * GP + jj;
                    #pragma unroll
                    for (int q = 0; q < 7; q++) g[q] += gr[q * 16];
                }
                float dt = p ? dtB : dtA;
                float iv = sigf(g[0]), fv = sigf(g[1]), zv = tanhx(g[2]), ov = sigf(g[3]);
                float ib = sigf(g[4]), fb = sigf(g[5]), de = softplusf(g[6]);
                float ci  = fv * cst[p] + iv * zv;
                float cb2 = fb * cbst[p] + ib * zv;
                float ct  = cb2 + (ci - cb2) * __expf(-de * dt);
                float hn  = ov * tanhx(ct);
                cst[p] = ct; cbst[p] = cb2;
                civ[p] = ci; cbv[p] = cb2; dev[p] = de; ovv[p] = ov;
                size_t idx = (size_t)t * (B_ * H_) + (size_t)(p ? bB : bA) * H_ + hid;
                if (p) idxB = idx; else idxA = idx;
                h_out[idx] = hn;   // critical-path store first
            }
        }
        __syncthreads();

        // ---- group barrier: arrive early, overlap remaining stores, wait late ----
        unsigned mygen = 0;
        if (tid == 0) {
            __threadfence();
            mygen = *genp;
            if (atomicAdd(cntp, 1u) == 15u) {
                *cntp = 0u;
                __threadfence();
                *genp = mygen + 1u;
            }
        }
        c_out[idxA]  = civ[0];  c_out[idxB]  = civ[1];
        cb_out[idxA] = cbv[0];  cb_out[idxB] = cbv[1];
        de_out[idxA] = dev[0];  de_out[idxB] = dev[1];
        o_out[idxA]  = ovv[0];  o_out[idxB]  = ovv[1];
        if (tid == 0) {
            while (*genp == mygen) {}
            __threadfence();
        }
        __syncthreads();
    }

    full_barrier();

    // ---- Phase 2: intensity = softplus(h_out @ W_lam + b_lam), tf32 HMMA ----
    {
        float2* WfL = (float2*)(smem + OFF_WFL);
        float*  h2  = (float*)(smem + OFF_H2);
        const int mw2 = wid & 3, nw2 = wid >> 2;
        for (int e = tid; e < 16 * 32 * 32; e += TB) {
            int nf = e >> 10, kf = (e >> 5) & 31, ln = e & 31;
            int g8 = ln >> 2, t4 = ln & 3;
            int n = nf * 8 + g8;
            int k = kf * 8 + t4;
            float x = Wl[(size_t)k * NTY + n];
            float y = Wl[(size_t)(k + 4) * NTY + n];
            WfL[e] = make_float2(tf(x), tf(y));
        }
        __syncthreads();

        const int NTILE = (T_ * B_) / 64;   // 4088
        for (int mt = blockIdx.x; mt < NTILE; mt += NBLK) {
            int r0t = mt * 64;
            int tt = r0t >> 9;
            int b0 = r0t & 511;
            {
                int row = tid >> 3, inner = tid & 7;
                const float4* src = (const float4*)(h_out + (size_t)tt * (B_ * H_)
                                                    + (size_t)(b0 + row) * H_);
                float* dst = h2 + row * HP;
                #pragma unroll
                for (int j = 0; j < 8; j++) {
                    int c4 = inner + 8 * j;
                    float4 v = __ldcg(src + c4);
                    v.x = tf(v.x); v.y = tf(v.y); v.z = tf(v.z); v.w = tf(v.w);
                    *(float4*)(dst + c4 * 4) = v;
                }
            }
            __syncthreads();
            float d[4][4];
            #pragma unroll
            for (int q = 0; q < 4; q++)
                #pragma unroll
                for (int r2 = 0; r2 < 4; r2++) d[q][r2] = 0.f;
            const float*  hrow = h2 + (mw2 * 16 + gid) * HP + tig;
            const float2* wb   = WfL + (size_t)(nw2 * 4) * 1024 + lane;
            #pragma unroll 2
            for (int kf = 0; kf < 32; kf++) {
                unsigned a0 = __float_as_uint(hrow[kf * 8]);
                unsigned a1 = __float_as_uint(hrow[kf * 8 + 8 * HP]);
                unsigned a2 = __float_as_uint(hrow[kf * 8 + 4]);
                unsigned a3 = __float_as_uint(hrow[kf * 8 + 8 * HP + 4]);
                #pragma unroll
                for (int q = 0; q < 4; q++) {
                    float2 bv = wb[(q * 32 + kf) * 32];
                    mma8(d[q], a0, a1, a2, a3, __float_as_uint(bv.x), __float_as_uint(bv.y));
                }
            }
            int rl = mw2 * 16 + gid;
            #pragma unroll
            for (int q = 0; q < 4; q++) {
                int n0 = (nw2 * 4 + q) * 8 + 2 * tig;
                float bv0 = __ldg(bl + n0), bv1 = __ldg(bl + n0 + 1);
                size_t base = (size_t)(b0 + rl) * (T_ * NTY) + (size_t)tt * NTY + n0;
                *(float2*)(intens + base) =
                    make_float2(softplusf(d[q][0] + bv0), softplusf(d[q][1] + bv1));
                size_t base2 = base + (size_t)8 * (T_ * NTY);
                *(float2*)(intens + base2) =
                    make_float2(softplusf(d[q][2] + bv0), softplusf(d[q][3] + bv1));
            }
            __syncthreads();
        }
    }
}

extern "C" void kernel_launch(void* const* d_in, const int* in_sizes, int n_in,
                              void* d_out, int out_size) {
    const int*   types = (const int*)d_in[0];
    const float* dtime = (const float*)d_in[1];
    const float* emb   = (const float*)d_in[2];
    const float* Wc    = (const float*)d_in[3];
    const float* bc    = (const float*)d_in[4];
    const float* Wl    = (const float*)d_in[5];
    const float* bl    = (const float*)d_in[6];
    cudaFuncSetAttribute(ctlstm_kernel, cudaFuncAttributeMaxDynamicSharedMemorySize, SMEM_BYTES);
    ctlstm_kernel<<<NBLK, TB, SMEM_BYTES>>>(types, dtime, emb, Wc, bc, Wl, bl, (float*)d_out);
}

// round 7
// speedup vs baseline: 2.0164x; 1.0208x over previous
#include <cuda_runtime.h>
#include <cstdint>

#define NBLK 128
#define TB   512
#define B_   512
#define S_   512
#define T_   511
#define H_   256
#define NTY  128
#define NG   1792
#define HP   260
#define GP   116

// ---- scan-phase smem ----
#define OFF_WF  0            // 14 nf x 8 kf2 x 32 lanes x uint4 = 57344 B
#define OFF_AF  57344        // 4 mt x 16 kf x 32 lanes x uint4 = 32768 B
#define OFF_GTS 90112        // 64 x 116 x 4 = 29696 B
// ---- phase-2 smem ----
#define OFF_WFL 0
#define OFF_H2  131072
#define SMEM_BYTES 197632

__device__ __align__(16) float g_P[NTY * NG];
__device__ __align__(16) uint32_t g_hx[2][B_ * H_ / 2];   // bf16x2-packed h exchange
__device__ unsigned g_cnt_full = 0;
__device__ unsigned g_gen_full = 0;
__device__ unsigned g_cnt_grp[256];
__device__ unsigned g_gen_grp[256];

__device__ __forceinline__ unsigned f2tf32(float x) {
    unsigned u;
    asm("cvt.rna.tf32.f32 %0, %1;" : "=r"(u) : "f"(x));
    return u;
}
__device__ __forceinline__ float tf(float x) { return __uint_as_float(f2tf32(x)); }

// pack two f32 into bf16x2: lo -> lower half, hi -> upper half
__device__ __forceinline__ unsigned packbf(float lo, float hi) {
    unsigned r;
    asm("cvt.rn.bf16x2.f32 %0, %1, %2;" : "=r"(r) : "f"(hi), "f"(lo));
    return r;
}

__device__ __forceinline__ void mma16(float* d, uint4 a, unsigned b0, unsigned b1) {
    asm volatile(
        "mma.sync.aligned.m16n8k16.row.col.f32.bf16.bf16.f32 "
        "{%0,%1,%2,%3}, {%4,%5,%6,%7}, {%8,%9}, {%0,%1,%2,%3};"
        : "+f"(d[0]), "+f"(d[1]), "+f"(d[2]), "+f"(d[3])
        : "r"(a.x), "r"(a.y), "r"(a.z), "r"(a.w), "r"(b0), "r"(b1));
}
__device__ __forceinline__ void mma8(float* d, unsigned a0, unsigned a1, unsigned a2, unsigned a3,
                                     unsigned b0, unsigned b1) {
    asm volatile(
        "mma.sync.aligned.m16n8k8.row.col.f32.tf32.tf32.f32 "
        "{%0,%1,%2,%3}, {%4,%5,%6,%7}, {%8,%9}, {%0,%1,%2,%3};"
        : "+f"(d[0]), "+f"(d[1]), "+f"(d[2]), "+f"(d[3])
        : "r"(a0), "r"(a1), "r"(a2), "r"(a3), "r"(b0), "r"(b1));
}

__device__ __forceinline__ float sigf(float x)   { return __fdividef(1.0f, 1.0f + __expf(-x)); }
__device__ __forceinline__ float tanhx(float x)  { return 1.0f - __fdividef(2.0f, __expf(2.0f * x) + 1.0f); }
__device__ __forceinline__ float softplusf(float x) {
    return x > 15.0f ? x : __logf(1.0f + __expf(x));
}

__device__ __forceinline__ void full_barrier() {
    __syncthreads();
    if (threadIdx.x == 0) {
        volatile unsigned* genp = &g_gen_full;
        unsigned gen = *genp;
        __threadfence();
        if (atomicAdd(&g_cnt_full, 1u) == NBLK - 1u) {
            g_cnt_full = 0u;
            __threadfence();
            *genp = gen + 1u;
        } else {
            while (*genp == gen) {}
        }
        __threadfence();
    }
    __syncthreads();
}

__global__ void __launch_bounds__(TB, 1)
ctlstm_kernel(const int* __restrict__ types, const float* __restrict__ dtime,
              const float* __restrict__ emb, const float* __restrict__ Wc,
              const float* __restrict__ bc, const float* __restrict__ Wl,
              const float* __restrict__ bl, float* __restrict__ out)
{
    extern __shared__ __align__(1024) char smem[];
    const int tid  = threadIdx.x;
    const int wid  = tid >> 5;
    const int lane = tid & 31;
    const int gid  = lane >> 2;
    const int tig  = lane & 3;
    const int bb   = blockIdx.x >> 4;   // batch tile 0..7 (64 rows)
    const int hb   = blockIdx.x & 15;   // hidden tile 0..15 (16 hids)

    float* intens = out;
    float* h_out  = out + (size_t)B_ * T_ * NTY;
    const size_t CH = (size_t)T_ * B_ * H_;
    float* c_out  = h_out + CH;
    float* cb_out = h_out + 2 * CH;
    float* de_out = h_out + 3 * CH;
    float* o_out  = h_out + 4 * CH;

    // ---- Phase 0a: pack W_h slice -> bf16 B fragments, permuted k layout ----
    // slot (kf, kh, t4) holds k-pair w = kf*8 + kh*4 + ((t4 - (kf&3)) & 3); k = 2w, 2w+1
    for (int e = tid; e < 14 * 8 * 32; e += TB) {
        int nf  = e >> 8;
        int kf2 = (e >> 5) & 7;
        int ln  = e & 31;
        int g8  = ln >> 2, t4 = ln & 3;
        int q = nf >> 1;
        int n = q * H_ + hb * 16 + (nf & 1) * 8 + g8;
        const float* Wh = Wc + (size_t)H_ * NG + n;
        unsigned bw[4];
        #pragma unroll
        for (int kk = 0; kk < 2; kk++) {
            int kf = 2 * kf2 + kk;
            #pragma unroll
            for (int kh = 0; kh < 2; kh++) {
                int w  = kf * 8 + kh * 4 + ((t4 - (kf & 3)) & 3);
                int k0 = 2 * w;
                bw[kk * 2 + kh] = packbf(Wh[(size_t)k0 * NG], Wh[(size_t)(k0 + 1) * NG]);
            }
        }
        ((uint4*)(smem + OFF_WF))[e] = make_uint4(bw[0], bw[1], bw[2], bw[3]);
    }
    // ---- Phase 0b: P[type] = emb_table[type] @ W_x + b_cell (1 type / block) ----
    {
        float* scr = (float*)(smem + OFF_AF);
        int ty = blockIdx.x;
        if (tid < H_) scr[tid] = emb[ty * H_ + tid];
        __syncthreads();
        for (int n = tid; n < NG; n += TB) {
            float acc = bc[n];
            #pragma unroll 8
            for (int k = 0; k < H_; k++) acc = fmaf(scr[k], Wc[(size_t)k * NG + n], acc);
            g_P[ty * NG + n] = acc;
        }
        __syncthreads();
    }
    full_barrier();

    // ---- Phase 1: sequential CT-LSTM scan ----
    const int mw = wid & 1;             // M half
    const int nw = wid >> 1;            // N quarter
    // elementwise map: 1 row x 2 hids per thread
    const int rb2 = tid >> 3;           // row 0..63
    const int hp  = tid & 7;            // hid pair 0..7
    const int b2  = bb * 64 + rb2;
    const int hid0 = hb * 16 + hp * 2;

    // staging map: warp covers rows mt*16 + {2q, 2q+1, 2q+8, 2q+9}
    const int s_mt   = wid >> 2;
    const int s_q    = wid & 3;
    const int s_rr   = lane >> 3;
    const int s_i    = lane & 7;
    const int s_gid  = 2 * s_q + (s_rr & 1);
    const int s_half = s_rr >> 1;
    const int s_row  = s_mt * 16 + s_half * 8 + s_gid;
    const int s_sq   = s_i >> 1;
    uint32_t* AFw = (uint32_t*)(smem + OFF_AF);
    const uint32_t s_base = s_mt * 2048 + s_gid * 16 + (s_i & 1) * 2 + s_half + s_sq * 128;

    float cst0 = 0.f, cst1 = 0.f, cbst0 = 0.f, cbst1 = 0.f;

    volatile unsigned* genp = &g_gen_grp[bb * 32];
    unsigned* cntp = &g_cnt_grp[bb * 32];

    for (int t = 0; t < T_; t++) {
        // ---- prefetch gate-independent operands ----
        int   ty = __ldg(types + (size_t)b2 * S_ + t);
        float dt = __ldg(dtime + (size_t)b2 * S_ + t + 1);
        float2 pg[7];
        {
            const float2* Pr = (const float2*)(g_P + (size_t)ty * NG + hid0);
            #pragma unroll
            for (int q = 0; q < 7; q++) pg[q] = __ldg(Pr + q * (H_ / 2));
        }

        if (t > 0) {
            // ---- stage bf16 h_{t-1} -> A fragments (conflict-free scatter) ----
            {
                const uint4* src = (const uint4*)(g_hx[(t - 1) & 1]
                                                  + (size_t)(bb * 64 + s_row) * 128);
                #pragma unroll
                for (int j = 0; j < 4; j++) {
                    uint4 v = __ldcg(src + s_i + 8 * j);
                    uint32_t a = s_base + j * 512;
                    AFw[a + (((s_sq + 0) & 3) << 2)] = v.x;
                    AFw[a + (((s_sq + 1) & 3) << 2)] = v.y;
                    AFw[a + (((s_sq + 2) & 3) << 2)] = v.z;
                    AFw[a + (((s_sq + 3) & 3) << 2)] = v.w;
                }
            }
            __syncthreads();

            // ---- gates = h @ W_h : warps 0..7, each m32 x n32, bf16 m16n8k16 ----
            if (wid < 8) {
                float acc[2][4][4];
                #pragma unroll
                for (int m = 0; m < 2; m++)
                    #pragma unroll
                    for (int f = 0; f < 4; f++)
                        #pragma unroll
                        for (int r2 = 0; r2 < 4; r2++) acc[m][f][r2] = 0.f;
                const uint4* AFp = (const uint4*)(smem + OFF_AF) + (mw * 2 * 16) * 32 + lane;
                const uint4* WFp = (const uint4*)(smem + OFF_WF) + (nw * 4 * 8) * 32 + lane;
                #pragma unroll
                for (int kf2 = 0; kf2 < 8; kf2++) {
                    uint4 bv[4];
                    #pragma unroll
                    for (int f = 0; f < 4; f++) bv[f] = WFp[(f * 8 + kf2) * 32];
                    uint4 a0e = AFp[(2 * kf2) * 32];
                    uint4 a0o = AFp[(2 * kf2 + 1) * 32];
                    uint4 a1e = AFp[(16 + 2 * kf2) * 32];
                    uint4 a1o = AFp[(16 + 2 * kf2 + 1) * 32];
                    #pragma unroll
                    for (int f = 0; f < 4; f++) {
                        mma16(acc[0][f], a0e, bv[f].x, bv[f].y);
                        mma16(acc[1][f], a1e, bv[f].x, bv[f].y);
                        mma16(acc[0][f], a0o, bv[f].z, bv[f].w);
                        mma16(acc[1][f], a1o, bv[f].z, bv[f].w);
                    }
                }
                float* g = (float*)(smem + OFF_GTS);
                #pragma unroll
                for (int m = 0; m < 2; m++) {
                    #pragma unroll
                    for (int f = 0; f < 4; f++) {
                        int fg = nw * 4 + f;
                        if (fg < 14) {
                            int c  = fg * 8 + 2 * tig;
                            int r0 = mw * 32 + m * 16 + gid;
                            *(float2*)(g + r0 * GP + c)       = make_float2(acc[m][f][0], acc[m][f][1]);
                            *(float2*)(g + (r0 + 8) * GP + c) = make_float2(acc[m][f][2], acc[m][f][3]);
                        }
                    }
                }
            }
            __syncthreads();
        }

        // ---- elementwise CT-LSTM update (1 row x 2 hids per thread) ----
        float g0[7], g1[7];
        if (t > 0) {
            const float* gr = (const float*)(smem + OFF_GTS) + rb2 * GP + hp * 2;
            #pragma unroll
            for (int q = 0; q < 7; q++) {
                float2 v = *(const float2*)(gr + q * 16);
                g0[q] = v.x + pg[q].x;
                g1[q] = v.y + pg[q].y;
            }
        } else {
            #pragma unroll
            for (int q = 0; q < 7; q++) { g0[q] = pg[q].x; g1[q] = pg[q].y; }
        }
        float hn0, hn1, ci0, ci1, cb0, cb1, de0, de1, ov0, ov1;
        {
            float iv = sigf(g0[0]), fv = sigf(g0[1]), zv = tanhx(g0[2]);
            ov0 = sigf(g0[3]);
            float ib = sigf(g0[4]), fb = sigf(g0[5]);
            de0 = softplusf(g0[6]);
            ci0 = fv * cst0 + iv * zv;
            cb0 = fb * cbst0 + ib * zv;
            float ct = cb0 + (ci0 - cb0) * __expf(-de0 * dt);
            hn0 = ov0 * tanhx(ct);
            cst0 = ct; cbst0 = cb0;
        }
        {
            float iv = sigf(g1[0]), fv = sigf(g1[1]), zv = tanhx(g1[2]);
            ov1 = sigf(g1[3]);
            float ib = sigf(g1[4]), fb = sigf(g1[5]);
            de1 = softplusf(g1[6]);
            ci1 = fv * cst1 + iv * zv;
            cb1 = fb * cbst1 + ib * zv;
            float ct = cb1 + (ci1 - cb1) * __expf(-de1 * dt);
            hn1 = ov1 * tanhx(ct);
            cst1 = ct; cbst1 = cb1;
        }
        // critical-path: packed h to exchange scratch
        g_hx[t & 1][(size_t)b2 * 128 + hb * 8 + hp] = packbf(hn0, hn1);
        __syncthreads();

        // ---- group barrier: arrive early, overlap remaining stores, wait late ----
        unsigned mygen = 0;
        if (tid == 0) {
            __threadfence();
            mygen = *genp;
            if (atomicAdd(cntp, 1u) == 15u) {
                *cntp = 0u;
                __threadfence();
                *genp = mygen + 1u;
            }
        }
        {
            size_t idx = (size_t)t * (B_ * H_) + (size_t)b2 * H_ + hid0;
            *(float2*)(h_out  + idx) = make_float2(hn0, hn1);
            *(float2*)(c_out  + idx) = make_float2(ci0, ci1);
            *(float2*)(cb_out + idx) = make_float2(cb0, cb1);
            *(float2*)(de_out + idx) = make_float2(de0, de1);
            *(float2*)(o_out  + idx) = make_float2(ov0, ov1);
        }
        if (tid == 0) {
            while (*genp == mygen) {}
            __threadfence();
        }
        __syncthreads();
    }

    full_barrier();

    // ---- Phase 2: intensity = softplus(h_out @ W_lam + b_lam), tf32 HMMA ----
    {
        float2* WfL = (float2*)(smem + OFF_WFL);
        float*  h2  = (float*)(smem + OFF_H2);
        const int mw2 = wid & 3, nw2 = wid >> 2;
        for (int e = tid; e < 16 * 32 * 32; e += TB) {
            int nf = e >> 10, kf = (e >> 5) & 31, ln = e & 31;
            int g8 = ln >> 2, t4 = ln & 3;
            int n = nf * 8 + g8;
            int k = kf * 8 + t4;
            float x = Wl[(size_t)k * NTY + n];
            float y = Wl[(size_t)(k + 4) * NTY + n];
            WfL[e] = make_float2(tf(x), tf(y));
        }
        __syncthreads();

        const int NTILE = (T_ * B_) / 64;   // 4088
        for (int mt = blockIdx.x; mt < NTILE; mt += NBLK) {
            int r0t = mt * 64;
            int tt = r0t >> 9;
            int b0 = r0t & 511;
            {
                int row = tid >> 3, inner = tid & 7;
                const float4* src = (const float4*)(h_out + (size_t)tt * (B_ * H_)
                                                    + (size_t)(b0 + row) * H_);
                float* dst = h2 + row * HP;
                #pragma unroll
                for (int j = 0; j < 8; j++) {
                    int c4 = inner + 8 * j;
                    float4 v = __ldcg(src + c4);
                    v.x = tf(v.x); v.y = tf(v.y); v.z = tf(v.z); v.w = tf(v.w);
                    *(float4*)(dst + c4 * 4) = v;
                }
            }
            __syncthreads();
            float d[4][4];
            #pragma unroll
            for (int q = 0; q < 4; q++)
                #pragma unroll
                for (int r2 = 0; r2 < 4; r2++) d[q][r2] = 0.f;
            const float*  hrow = h2 + (mw2 * 16 + gid) * HP + tig;
            const float2* wb   = WfL + (size_t)(nw2 * 4) * 1024 + lane;
            #pragma unroll 2
            for (int kf = 0; kf < 32; kf++) {
                unsigned a0 = __float_as_uint(hrow[kf * 8]);
                unsigned a1 = __float_as_uint(hrow[kf * 8 + 8 * HP]);
                unsigned a2 = __float_as_uint(hrow[kf * 8 + 4]);
                unsigned a3 = __float_as_uint(hrow[kf * 8 + 8 * HP + 4]);
                #pragma unroll
                for (int q = 0; q < 4; q++) {
                    float2 bv = wb[(q * 32 + kf) * 32];
                    mma8(d[q], a0, a1, a2, a3, __float_as_uint(bv.x), __float_as_uint(bv.y));
                }
            }
            int rl = mw2 * 16 + gid;
            #pragma unroll
            for (int q = 0; q < 4; q++) {
                int n0 = (nw2 * 4 + q) * 8 + 2 * tig;
                float bv0 = __ldg(bl + n0), bv1 = __ldg(bl + n0 + 1);
                size_t base = (size_t)(b0 + rl) * (T_ * NTY) + (size_t)tt * NTY + n0;
                *(float2*)(intens + base) =
                    make_float2(softplusf(d[q][0] + bv0), softplusf(d[q][1] + bv1));
                size_t base2 = base + (size_t)8 * (T_ * NTY);
                *(float2*)(intens + base2) =
                    make_float2(softplusf(d[q][2] + bv0), softplusf(d[q][3] + bv1));
            }
            __syncthreads();
        }
    }
}

extern "C" void kernel_launch(void* const* d_in, const int* in_sizes, int n_in,
                              void* d_out, int out_size) {
    const int*   types = (const int*)d_in[0];
    const float* dtime = (const float*)d_in[1];
    const float* emb   = (const float*)d_in[2];
    const float* Wc    = (const float*)d_in[3];
    const float* bc    = (const float*)d_in[4];
    const float* Wl    = (const float*)d_in[5];
    const float* bl    = (const float*)d_in[6];
    cudaFuncSetAttribute(ctlstm_kernel, cudaFuncAttributeMaxDynamicSharedMemorySize, SMEM_BYTES);
    ctlstm_kernel<<<NBLK, TB, SMEM_BYTES>>>(types, dtime, emb, Wc, bc, Wl, bl, (float*)d_out);
}

// round 9
// speedup vs baseline: 2.7324x; 1.3551x over previous
#include <cuda_runtime.h>
#include <cstdint>

#define NBLK 128
#define TB   512
#define B_   512
#define S_   512
#define T_   511
#define H_   256
#define NTY  128
#define NG   1792
#define HP   260
#define GP   116

// ---- scan-phase smem ----
#define OFF_WF  0            // 14 nf x 8 kf2 x 32 lanes x uint4 = 57344 B
#define OFF_AF  57344        // 4 mt x 16 kf x 32 lanes x uint4 = 32768 B
#define OFF_GTS 90112        // 64 x 116 x 4 = 29696 B
// ---- phase-2 smem ----
#define OFF_WFL 0
#define OFF_H2  131072
#define SMEM_BYTES 197632

__device__ __align__(16) float g_P[NTY * NG];
__device__ __align__(16) uint32_t g_hx[2][B_ * H_ / 2];   // bf16x2-packed h exchange
__device__ unsigned g_cnt_full = 0;
__device__ unsigned g_gen_full = 0;
__device__ __align__(64) unsigned g_flag[8 * 16];          // per-group arrival flags

__device__ __forceinline__ unsigned f2tf32(float x) {
    unsigned u;
    asm("cvt.rna.tf32.f32 %0, %1;" : "=r"(u) : "f"(x));
    return u;
}
__device__ __forceinline__ float tf(float x) { return __uint_as_float(f2tf32(x)); }

__device__ __forceinline__ unsigned packbf(float lo, float hi) {
    unsigned r;
    asm("cvt.rn.bf16x2.f32 %0, %1, %2;" : "=r"(r) : "f"(hi), "f"(lo));
    return r;
}

__device__ __forceinline__ void mma16(float* d, uint4 a, unsigned b0, unsigned b1) {
    asm volatile(
        "mma.sync.aligned.m16n8k16.row.col.f32.bf16.bf16.f32 "
        "{%0,%1,%2,%3}, {%4,%5,%6,%7}, {%8,%9}, {%0,%1,%2,%3};"
        : "+f"(d[0]), "+f"(d[1]), "+f"(d[2]), "+f"(d[3])
        : "r"(a.x), "r"(a.y), "r"(a.z), "r"(a.w), "r"(b0), "r"(b1));
}
__device__ __forceinline__ void mma8(float* d, unsigned a0, unsigned a1, unsigned a2, unsigned a3,
                                     unsigned b0, unsigned b1) {
    asm volatile(
        "mma.sync.aligned.m16n8k8.row.col.f32.tf32.tf32.f32 "
        "{%0,%1,%2,%3}, {%4,%5,%6,%7}, {%8,%9}, {%0,%1,%2,%3};"
        : "+f"(d[0]), "+f"(d[1]), "+f"(d[2]), "+f"(d[3])
        : "r"(a0), "r"(a1), "r"(a2), "r"(a3), "r"(b0), "r"(b1));
}

__device__ __forceinline__ float sigf(float x)   { return __fdividef(1.0f, 1.0f + __expf(-x)); }
__device__ __forceinline__ float tanhx(float x)  { return 1.0f - __fdividef(2.0f, __expf(2.0f * x) + 1.0f); }
__device__ __forceinline__ float softplusf(float x) {
    return x > 15.0f ? x : __logf(1.0f + __expf(x));
}

__device__ __forceinline__ void full_barrier() {
    __syncthreads();
    if (threadIdx.x == 0) {
        volatile unsigned* genp = &g_gen_full;
        unsigned gen = *genp;
        __threadfence();
        if (atomicAdd(&g_cnt_full, 1u) == NBLK - 1u) {
            g_cnt_full = 0u;
            __threadfence();
            *genp = gen + 1u;
        } else {
            while (*genp == gen) {}
        }
        __threadfence();
    }
    __syncthreads();
}

__global__ void __launch_bounds__(TB, 1)
ctlstm_kernel(const int* __restrict__ types, const float* __restrict__ dtime,
              const float* __restrict__ emb, const float* __restrict__ Wc,
              const float* __restrict__ bc, const float* __restrict__ Wl,
              const float* __restrict__ bl, float* __restrict__ out)
{
    extern __shared__ __align__(1024) char smem[];
    const int tid  = threadIdx.x;
    const int wid  = tid >> 5;
    const int lane = tid & 31;
    const int gid  = lane >> 2;
    const int tig  = lane & 3;
    const int bb   = blockIdx.x >> 4;   // batch tile 0..7 (64 rows)
    const int hb   = blockIdx.x & 15;   // hidden tile 0..15 (16 hids)

    float* intens = out;
    float* h_out  = out + (size_t)B_ * T_ * NTY;
    const size_t CH = (size_t)T_ * B_ * H_;
    float* c_out  = h_out + CH;
    float* cb_out = h_out + 2 * CH;
    float* de_out = h_out + 3 * CH;
    float* o_out  = h_out + 4 * CH;

    // flag base: all slots are uniform at launch entry (monotonic across replays)
    const unsigned fbase = g_flag[bb * 16 + hb];

    // ---- Phase 0a: pack W_h slice -> bf16 B fragments, permuted k layout ----
    // slot (kf, kh, t4) holds k-pair w = kf*8 + kh*4 + ((t4 - (kf&3)) & 3); k = 2w, 2w+1
    for (int e = tid; e < 14 * 8 * 32; e += TB) {
        int nf  = e >> 8;
        int kf2 = (e >> 5) & 7;
        int ln  = e & 31;
        int g8  = ln >> 2, t4 = ln & 3;
        int q = nf >> 1;
        int n = q * H_ + hb * 16 + (nf & 1) * 8 + g8;
        const float* Wh = Wc + (size_t)H_ * NG + n;
        unsigned bw[4];
        #pragma unroll
        for (int kk = 0; kk < 2; kk++) {
            int kf = 2 * kf2 + kk;
            #pragma unroll
            for (int kh = 0; kh < 2; kh++) {
                int w  = kf * 8 + kh * 4 + ((t4 - (kf & 3)) & 3);
                int k0 = 2 * w;
                bw[kk * 2 + kh] = packbf(Wh[(size_t)k0 * NG], Wh[(size_t)(k0 + 1) * NG]);
            }
        }
        ((uint4*)(smem + OFF_WF))[e] = make_uint4(bw[0], bw[1], bw[2], bw[3]);
    }
    // ---- Phase 0b: P[type] = emb_table[type] @ W_x + b_cell (1 type / block) ----
    {
        float* scr = (float*)(smem + OFF_AF);
        int ty = blockIdx.x;
        if (tid < H_) scr[tid] = emb[ty * H_ + tid];
        __syncthreads();
        for (int n = tid; n < NG; n += TB) {
            float acc = bc[n];
            #pragma unroll 8
            for (int k = 0; k < H_; k++) acc = fmaf(scr[k], Wc[(size_t)k * NG + n], acc);
            g_P[ty * NG + n] = acc;
        }
        __syncthreads();
    }
    full_barrier();

    // ---- Phase 1: sequential CT-LSTM scan ----
    const int mw = wid & 1;             // M half
    const int nw = wid >> 1;            // N quarter
    // elementwise map: 1 row x 2 hids per thread
    const int rb2 = tid >> 3;           // row 0..63
    const int hp  = tid & 7;            // hid pair 0..7
    const int b2  = bb * 64 + rb2;
    const int hid0 = hb * 16 + hp * 2;

    // staging map: warp covers rows mt*16 + {2q, 2q+1, 2q+8, 2q+9}
    const int s_mt   = wid >> 2;
    const int s_q    = wid & 3;
    const int s_rr   = lane >> 3;
    const int s_i    = lane & 7;
    const int s_gid  = 2 * s_q + (s_rr & 1);
    const int s_half = s_rr >> 1;
    const int s_row  = s_mt * 16 + s_half * 8 + s_gid;
    const int s_sq   = s_i >> 1;
    uint32_t* AFw = (uint32_t*)(smem + OFF_AF);
    const uint32_t s_base = s_mt * 2048 + s_gid * 16 + (s_i & 1) * 2 + s_half + s_sq * 128;

    float cst0 = 0.f, cst1 = 0.f, cbst0 = 0.f, cbst1 = 0.f;

    unsigned* const myflag = g_flag + bb * 16 + hb;
    unsigned* const grpflags = g_flag + bb * 16;

    for (int t = 0; t < T_; t++) {
        // ---- prefetch gate-independent operands (issued BEFORE the wait) ----
        int   ty = __ldg(types + (size_t)b2 * S_ + t);
        float dt = __ldg(dtime + (size_t)b2 * S_ + t + 1);
        float2 pg[7];
        {
            const float2* Pr = (const float2*)(g_P + (size_t)ty * NG + hid0);
            #pragma unroll
            for (int q = 0; q < 7; q++) pg[q] = __ldg(Pr + q * (H_ / 2));
        }

        if (t > 0) {
            // ---- wait: all peers arrived step t-1 (parallel 16-lane poll) ----
            if (wid == 0 && lane < 16) {
                const unsigned tgt = fbase + (unsigned)t;
                unsigned v;
                do {
                    asm volatile("ld.acquire.gpu.global.u32 %0, [%1];"
                                 : "=r"(v) : "l"(grpflags + lane) : "memory");
                } while ((int)(v - tgt) < 0);
            }
            __syncthreads();

            // ---- stage bf16 h_{t-1} -> A fragments (conflict-free scatter) ----
            {
                const uint4* src = (const uint4*)(g_hx[(t - 1) & 1]
                                                  + (size_t)(bb * 64 + s_row) * 128);
                #pragma unroll
                for (int j = 0; j < 4; j++) {
                    uint4 v = __ldcg(src + s_i + 8 * j);
                    uint32_t a = s_base + j * 512;
                    AFw[a + (((s_sq + 0) & 3) << 2)] = v.x;
                    AFw[a + (((s_sq + 1) & 3) << 2)] = v.y;
                    AFw[a + (((s_sq + 2) & 3) << 2)] = v.z;
                    AFw[a + (((s_sq + 3) & 3) << 2)] = v.w;
                }
            }
            __syncthreads();

            // ---- gates = h @ W_h : warps 0..7, each m32 x n32, bf16 m16n8k16 ----
            if (wid < 8) {
                float acc[2][4][4];
                #pragma unroll
                for (int m = 0; m < 2; m++)
                    #pragma unroll
                    for (int f = 0; f < 4; f++)
                        #pragma unroll
                        for (int r2 = 0; r2 < 4; r2++) acc[m][f][r2] = 0.f;
                const uint4* AFp = (const uint4*)(smem + OFF_AF) + (mw * 2 * 16) * 32 + lane;
                const uint4* WFp = (const uint4*)(smem + OFF_WF) + (nw * 4 * 8) * 32 + lane;
                #pragma unroll
                for (int kf2 = 0; kf2 < 8; kf2++) {
                    uint4 bv[4];
                    #pragma unroll
                    for (int f = 0; f < 4; f++) bv[f] = WFp[(f * 8 + kf2) * 32];
                    uint4 a0e = AFp[(2 * kf2) * 32];
                    uint4 a0o = AFp[(2 * kf2 + 1) * 32];
                    uint4 a1e = AFp[(16 + 2 * kf2) * 32];
                    uint4 a1o = AFp[(16 + 2 * kf2 + 1) * 32];
                    #pragma unroll
                    for (int f = 0; f < 4; f++) {
                        mma16(acc[0][f], a0e, bv[f].x, bv[f].y);
                        mma16(acc[1][f], a1e, bv[f].x, bv[f].y);
                        mma16(acc[0][f], a0o, bv[f].z, bv[f].w);
                        mma16(acc[1][f], a1o, bv[f].z, bv[f].w);
                    }
                }
                float* g = (float*)(smem + OFF_GTS);
                #pragma unroll
                for (int m = 0; m < 2; m++) {
                    #pragma unroll
                    for (int f = 0; f < 4; f++) {
                        int fg = nw * 4 + f;
                        if (fg < 14) {
                            int c  = fg * 8 + 2 * tig;
                            int r0 = mw * 32 + m * 16 + gid;
                            *(float2*)(g + r0 * GP + c)       = make_float2(acc[m][f][0], acc[m][f][1]);
                            *(float2*)(g + (r0 + 8) * GP + c) = make_float2(acc[m][f][2], acc[m][f][3]);
                        }
                    }
                }
            }
            __syncthreads();
        }

        // ---- elementwise CT-LSTM update (1 row x 2 hids per thread) ----
        float g0[7], g1[7];
        if (t > 0) {
            const float* gr = (const float*)(smem + OFF_GTS) + rb2 * GP + hp * 2;
            #pragma unroll
            for (int q = 0; q < 7; q++) {
                float2 v = *(const float2*)(gr + q * 16);
                g0[q] = v.x + pg[q].x;
                g1[q] = v.y + pg[q].y;
            }
        } else {
            #pragma unroll
            for (int q = 0; q < 7; q++) { g0[q] = pg[q].x; g1[q] = pg[q].y; }
        }
        float hn0, hn1, ci0, ci1, cb0, cb1, de0, de1, ov0, ov1;
        {
            float iv = sigf(g0[0]), fv = sigf(g0[1]), zv = tanhx(g0[2]);
            ov0 = sigf(g0[3]);
            float ib = sigf(g0[4]), fb = sigf(g0[5]);
            de0 = softplusf(g0[6]);
            ci0 = fv * cst0 + iv * zv;
            cb0 = fb * cbst0 + ib * zv;
            float ct = cb0 + (ci0 - cb0) * __expf(-de0 * dt);
            hn0 = ov0 * tanhx(ct);
            cst0 = ct; cbst0 = cb0;
        }
        {
            float iv = sigf(g1[0]), fv = sigf(g1[1]), zv = tanhx(g1[2]);
            ov1 = sigf(g1[3]);
            float ib = sigf(g1[4]), fb = sigf(g1[5]);
            de1 = softplusf(g1[6]);
            ci1 = fv * cst1 + iv * zv;
            cb1 = fb * cbst1 + ib * zv;
            float ct = cb1 + (ci1 - cb1) * __expf(-de1 * dt);
            hn1 = ov1 * tanhx(ct);
            cst1 = ct; cbst1 = cb1;
        }
        // critical-path: packed h to exchange scratch
        g_hx[t & 1][(size_t)b2 * 128 + hb * 8 + hp] = packbf(hn0, hn1);
        __syncthreads();

        // ---- arrive (release), then overlap output stores with peer skew ----
        if (tid == 0) {
            asm volatile("st.release.gpu.global.u32 [%0], %1;"
                         :: "l"(myflag), "r"(fbase + (unsigned)t + 1u) : "memory");
        }
        {
            size_t idx = (size_t)t * (B_ * H_) + (size_t)b2 * H_ + hid0;
            *(float2*)(h_out  + idx) = make_float2(hn0, hn1);
            *(float2*)(c_out  + idx) = make_float2(ci0, ci1);
            *(float2*)(cb_out + idx) = make_float2(cb0, cb1);
            *(float2*)(de_out + idx) = make_float2(de0, de1);
            *(float2*)(o_out  + idx) = make_float2(ov0, ov1);
        }
        // wait deferred to top of next iteration (after its prefetch)
    }

    full_barrier();

    // ---- Phase 2: intensity = softplus(h_out @ W_lam + b_lam), tf32 HMMA ----
    {
        float2* WfL = (float2*)(smem + OFF_WFL);
        float*  h2  = (float*)(smem + OFF_H2);
        const int mw2 = wid & 3, nw2 = wid >> 2;
        for (int e = tid; e < 16 * 32 * 32; e += TB) {
            int nf = e >> 10, kf = (e >> 5) & 31, ln = e & 31;
            int g8 = ln >> 2, t4 = ln & 3;
            int n = nf * 8 + g8;
            int k = kf * 8 + t4;
            float x = Wl[(size_t)k * NTY + n];
            float y = Wl[(size_t)(k + 4) * NTY + n];
            WfL[e] = make_float2(tf(x), tf(y));
        }
        __syncthreads();

        const int NTILE = (T_ * B_) / 64;   // 4088
        for (int mt = blockIdx.x; mt < NTILE; mt += NBLK) {
            int r0t = mt * 64;
            int tt = r0t >> 9;
            int b0 = r0t & 511;
            {
                int row = tid >> 3, inner = tid & 7;
                const float4* src = (const float4*)(h_out + (size_t)tt * (B_ * H_)
                                                    + (size_t)(b0 + row) * H_);
                float* dst = h2 + row * HP;
                #pragma unroll
                for (int j = 0; j < 8; j++) {
                    int c4 = inner + 8 * j;
                    float4 v = __ldcg(src + c4);
                    v.x = tf(v.x); v.y = tf(v.y); v.z = tf(v.z); v.w = tf(v.w);
                    *(float4*)(dst + c4 * 4) = v;
                }
            }
            __syncthreads();
            float d[4][4];
            #pragma unroll
            for (int q = 0; q < 4; q++)
                #pragma unroll
                for (int r2 = 0; r2 < 4; r2++) d[q][r2] = 0.f;
            const float*  hrow = h2 + (mw2 * 16 + gid) * HP + tig;
            const float2* wb   = WfL + (size_t)(nw2 * 4) * 1024 + lane;
            #pragma unroll 2
            for (int kf = 0; kf < 32; kf++) {
                unsigned a0 = __float_as_uint(hrow[kf * 8]);
                unsigned a1 = __float_as_uint(hrow[kf * 8 + 8 * HP]);
                unsigned a2 = __float_as_uint(hrow[kf * 8 + 4]);
                unsigned a3 = __float_as_uint(hrow[kf * 8 + 8 * HP + 4]);
                #pragma unroll
                for (int q = 0; q < 4; q++) {
                    float2 bv = wb[(q * 32 + kf) * 32];
                    mma8(d[q], a0, a1, a2, a3, __float_as_uint(bv.x), __float_as_uint(bv.y));
                }
            }
            int rl = mw2 * 16 + gid;
            #pragma unroll
            for (int q = 0; q < 4; q++) {
                int n0 = (nw2 * 4 + q) * 8 + 2 * tig;
                float bv0 = __ldg(bl + n0), bv1 = __ldg(bl + n0 + 1);
                size_t base = (size_t)(b0 + rl) * (T_ * NTY) + (size_t)tt * NTY + n0;
                *(float2*)(intens + base) =
                    make_float2(softplusf(d[q][0] + bv0), softplusf(d[q][1] + bv1));
                size_t base2 = base + (size_t)8 * (T_ * NTY);
                *(float2*)(intens + base2) =
                    make_float2(softplusf(d[q][2] + bv0), softplusf(d[q][3] + bv1));
            }
            __syncthreads();
        }
    }
}

extern "C" void kernel_launch(void* const* d_in, const int* in_sizes, int n_in,
                              void* d_out, int out_size) {
    const int*   types = (const int*)d_in[0];
    const float* dtime = (const float*)d_in[1];
    const float* emb   = (const float*)d_in[2];
    const float* Wc    = (const float*)d_in[3];
    const float* bc    = (const float*)d_in[4];
    const float* Wl    = (const float*)d_in[5];
    const float* bl    = (const float*)d_in[6];
    cudaFuncSetAttribute(ctlstm_kernel, cudaFuncAttributeMaxDynamicSharedMemorySize, SMEM_BYTES);
    ctlstm_kernel<<<NBLK, TB, SMEM_BYTES>>>(types, dtime, emb, Wc, bc, Wl, bl, (float*)d_out);
}